// round 9
// baseline (speedup 1.0000x reference)
#include <cuda_runtime.h>
#include <cuda_bf16.h>
#include <cstdint>

// ---------------------------------------------------------------------------
// DeformableConv2d: B=8, C=64, H=W=128, O=64, K=3, stride=1, pad=1, dil=1
// Main contraction on tensor cores via warp-level mma.sync (bf16 2-way split,
// fp32 accum) — plain sm_80+ PTX, assembles under .target sm_100.
// ---------------------------------------------------------------------------

#define BB 8
#define CC 64
#define HH 128
#define WW 128
#define OO 64
#define KPAD 584  // 576 + 8 pad (ushort); row stride 1168B, 16B-aligned

// Scratch (static device globals; no runtime allocation)
__device__ float g_x[(size_t)BB * HH * WW * CC];    // x in NHWC
__device__ float g_off[(size_t)BB * HH * WW * 18];  // offsets, NHWC-18
// B fragments for mma.sync m16n8k16: [k16(36)][n8(8)][split(2)][lane(32)][reg(2)]
__device__ uint32_t g_wfrag[36 * 8 * 2 * 32 * 2];

// ---- f32x2 packed math helpers (for k_off) ---------------------------------
__device__ __forceinline__ void ffma2(unsigned long long& d, unsigned long long a,
                                      unsigned long long b) {
    asm("fma.rn.f32x2 %0, %1, %2, %0;" : "+l"(d) : "l"(a), "l"(b));
}
__device__ __forceinline__ unsigned long long pack2(float x, float y) {
    unsigned long long r;
    asm("mov.b64 %0, {%1, %2};" : "=l"(r) : "f"(x), "f"(y));
    return r;
}
__device__ __forceinline__ float2 unpack2(unsigned long long v) {
    float2 r;
    asm("mov.b64 {%0, %1}, %2;" : "=f"(r.x), "=f"(r.y) : "l"(v));
    return r;
}

// ---- tensor-core helpers ---------------------------------------------------
__device__ __forceinline__ void ldmat4(uint32_t* a, uint32_t addr) {
    asm volatile("ldmatrix.sync.aligned.m8n8.x4.shared.b16 {%0,%1,%2,%3}, [%4];"
                 : "=r"(a[0]), "=r"(a[1]), "=r"(a[2]), "=r"(a[3]) : "r"(addr));
}
__device__ __forceinline__ void mma16816(float* d, const uint32_t* a, uint2 b) {
    asm volatile(
        "mma.sync.aligned.m16n8k16.row.col.f32.bf16.bf16.f32 "
        "{%0,%1,%2,%3}, {%4,%5,%6,%7}, {%8,%9}, {%0,%1,%2,%3};"
        : "+f"(d[0]), "+f"(d[1]), "+f"(d[2]), "+f"(d[3])
        : "r"(a[0]), "r"(a[1]), "r"(a[2]), "r"(a[3]), "r"(b.x), "r"(b.y));
}
__device__ __forceinline__ uint32_t smem_u32(const void* p) {
    uint32_t a;
    asm("{ .reg .u64 t; cvta.to.shared.u64 t, %1; cvt.u32.u64 %0, t; }" : "=r"(a) : "l"(p));
    return a;
}

// ---------------------------------------------------------------------------
// Kernel 1: NCHW -> NHWC transpose of x
// ---------------------------------------------------------------------------
__global__ void k_transpose(const float* __restrict__ x) {
    __shared__ float tile[32][33];
    int bh = blockIdx.x;
    int w0 = blockIdx.y * 32;
    int c0 = blockIdx.z * 32;
    int b = bh >> 7;
    const float* src = x + ((size_t)(b * CC) * HH + (bh & 127)) * WW;
#pragma unroll
    for (int i = 0; i < 32; i += 8) {
        int c = c0 + threadIdx.y + i;
        tile[threadIdx.y + i][threadIdx.x] = src[(size_t)c * HH * WW + w0 + threadIdx.x];
    }
    __syncthreads();
    float* dst = g_x + (size_t)bh * WW * CC;
#pragma unroll
    for (int i = 0; i < 32; i += 8) {
        int w = w0 + threadIdx.y + i;
        dst[(size_t)w * CC + c0 + threadIdx.x] = tile[threadIdx.x][threadIdx.y + i];
    }
}

// ---------------------------------------------------------------------------
// Kernel 2: weight -> mma.sync B fragments (bf16 hi/lo), fragment-major order.
// thread 'lane' reg r holds B[k0][n],B[k0+1][n]; k0=(lane&3)*2+r*8, n=n8*8+(lane>>2).
// ---------------------------------------------------------------------------
__global__ void k_wfrag(const float* __restrict__ w) {
    int idx = blockIdx.x * 256 + threadIdx.x;  // over 36864
    if (idx >= 36 * 8 * 2 * 64) return;
    int reg = idx & 1;
    int lane = (idx >> 1) & 31;
    int split = (idx >> 6) & 1;
    int n8 = (idx >> 7) & 7;
    int k16 = idx >> 10;
    int n = n8 * 8 + (lane >> 2);
    int k0 = (lane & 3) * 2 + reg * 8;
    int kg = k16 * 16 + k0;
    int tap = kg >> 6;
    int c = kg & 63;
    float v0 = w[(n * CC + c) * 9 + tap];
    float v1 = w[(n * CC + c + 1) * 9 + tap];
    unsigned short u0, u1;
    if (split == 0) {
        u0 = __bfloat16_as_ushort(__float2bfloat16(v0));
        u1 = __bfloat16_as_ushort(__float2bfloat16(v1));
    } else {
        __nv_bfloat16 h0 = __float2bfloat16(v0), h1 = __float2bfloat16(v1);
        u0 = __bfloat16_as_ushort(__float2bfloat16(v0 - __bfloat162float(h0)));
        u1 = __bfloat16_as_ushort(__float2bfloat16(v1 - __bfloat162float(h1)));
    }
    g_wfrag[idx] = (uint32_t)u0 | ((uint32_t)u1 << 16);
}

// ---------------------------------------------------------------------------
// Kernel 3: offset-predictor conv, 4 pixels/thread for weight-LDS amortization.
// grid (W/16, H/64, B), block 256. Thread: col j0+(tid&15),
// rows i_base + (tid>>4)*4 + {0..3}. Weights staged in static smem (45KB);
// x read directly from g_x via L1 (rows re-hit in cache across taps).
// ---------------------------------------------------------------------------
__global__ __launch_bounds__(256) void k_off(const float* __restrict__ off_w,
                                             const float* __restrict__ off_b) {
    __shared__ float wo[9][64][20];  // 46080 B
    int tid = threadIdx.x;
    int b = blockIdx.z;
    int j = blockIdx.x * 16 + (tid & 15);
    int i0 = blockIdx.y * 64 + (tid >> 4) * 4;

    for (int idx = tid; idx < 9 * 64 * 20; idx += 256) {
        int tap = idx / 1280;
        int r = idx - tap * 1280;
        int c = r / 20;
        int oc = r - c * 20;
        wo[tap][c][oc] = (oc < 18) ? off_w[(oc * CC + c) * 9 + tap] : 0.f;
    }
    __syncthreads();

    unsigned long long acc[4][9];
#pragma unroll
    for (int t = 0; t < 9; t++) {
        unsigned long long bv = pack2(__ldg(&off_b[2 * t]), __ldg(&off_b[2 * t + 1]));
#pragma unroll
        for (int u = 0; u < 4; u++) acc[u][t] = bv;
    }

    const float* xb = g_x + (size_t)b * HH * WW * CC;
    for (int tap = 0; tap < 9; tap++) {
        int dy = tap / 3 - 1, dx = tap - (tap / 3) * 3 - 1;
        int x = j + dx;
        bool vx = (unsigned)x < WW;
        const float2* rowp[4];
        bool vld[4];
#pragma unroll
        for (int u = 0; u < 4; u++) {
            int y = i0 + u + dy;
            vld[u] = vx && ((unsigned)y < HH);
            rowp[u] = (const float2*)(xb + ((size_t)y * WW + x) * CC);
        }
#pragma unroll 2
        for (int c2 = 0; c2 < 32; c2++) {
            float2 xv[4];
#pragma unroll
            for (int u = 0; u < 4; u++)
                xv[u] = vld[u] ? __ldg(&rowp[u][c2]) : make_float2(0.f, 0.f);
            const ulonglong2* wv0 = (const ulonglong2*)wo[tap][c2 * 2];
            const ulonglong2* wv1 = (const ulonglong2*)wo[tap][c2 * 2 + 1];
#pragma unroll
            for (int q = 0; q < 5; q++) {
                ulonglong2 w0 = wv0[q];
                ulonglong2 w1 = wv1[q];
#pragma unroll
                for (int u = 0; u < 4; u++) {
                    unsigned long long xp0 = pack2(xv[u].x, xv[u].x);
                    unsigned long long xp1 = pack2(xv[u].y, xv[u].y);
                    ffma2(acc[u][2 * q], xp0, w0.x);
                    ffma2(acc[u][2 * q + 1], xp0, w0.y);
                    if (q < 4) {
                        ffma2(acc[u][2 * q], xp1, w1.x);
                        ffma2(acc[u][2 * q + 1], xp1, w1.y);
                    } else {
                        ffma2(acc[u][8], xp1, w1.x);
                        // acc[u][9] would be padding; w1.y hits pad zeros
                    }
                }
            }
        }
    }
#pragma unroll
    for (int u = 0; u < 4; u++) {
        float* outp = g_off + ((size_t)(b * HH + i0 + u) * WW + j) * 18;
#pragma unroll
        for (int t = 0; t < 9; t++) {
            float2 v = unpack2(acc[u][t]);
            outp[2 * t] = v.x;
            outp[2 * t + 1] = v.y;
        }
    }
}

// ---------------------------------------------------------------------------
// Kernel 4: main deformable conv, tensor-core contraction, 32-px tiles.
// grid (W/32, H, B), block 256, dynamic smem ~77KB.
// Phase 1: bilinear-gather -> bf16 hi/lo into samp_hi/lo[32][KPAD].
// Phase 2: warp w: M-tile mt=w>>2 (px mt*16..+15), n8 pair {2(w&3), 2(w&3)+1};
//          K-loop 36x m16n8k16, 6 MMAs/step (Ahi*Whi + Ahi*Wlo + Alo*Whi).
//          Warp pairs (w, w+4) load identical B fragments -> L1 hits.
// ---------------------------------------------------------------------------
#define SAMP_BYTES (32 * KPAD * 2)                  // 37376
#define OFFS_OFF (2 * SAMP_BYTES)                   // 74752
#define SMEM_MAIN (OFFS_OFF + 32 * 18 * 4)          // 77056

__global__ __launch_bounds__(256) void k_main(const float* __restrict__ bias,
                                              float* __restrict__ out) {
    extern __shared__ char sh[];
    unsigned short* samp_hi = (unsigned short*)sh;
    unsigned short* samp_lo = (unsigned short*)(sh + SAMP_BYTES);
    float* offs = (float*)(sh + OFFS_OFF);  // [32][18]

    int tid = threadIdx.x;
    int b = blockIdx.z, i = blockIdx.y, j0 = blockIdx.x * 32;

    for (int idx = tid; idx < 32 * 18; idx += 256)
        offs[idx] = g_off[((size_t)(b * HH + i) * WW + j0) * 18 + idx];
    __syncthreads();

    // ---------------- Phase 1: gather (bf16 hi/lo) ----------------
    {
        int g = tid >> 4, lane = tid & 15;  // g: 0..15
        const float* xb = g_x + (size_t)b * HH * WW * CC;
#pragma unroll 2
        for (int it = 0; it < 18; it++) {
            int pk = it * 16 + g;  // 0..287
            int p = pk / 9, k = pk - p * 9;
            float oy = offs[p * 18 + 2 * k], ox = offs[p * 18 + 2 * k + 1];
            float sy = (float)(i + k / 3) + oy;
            float sx = (float)(j0 + p + (k - (k / 3) * 3)) + ox;
            float fy = floorf(sy), fx = floorf(sx);
            float wy1 = sy - fy, wx1 = sx - fx;
            float wy0 = 1.f - wy1, wx0 = 1.f - wx1;
            int iy = (int)fy, ix = (int)fx;
            float tw[4] = {wy0 * wx0, wy0 * wx1, wy1 * wx0, wy1 * wx1};
            int ty[4] = {iy, iy, iy + 1, iy + 1};
            int tx[4] = {ix, ix + 1, ix, ix + 1};
            float acc[4] = {0.f, 0.f, 0.f, 0.f};
#pragma unroll
            for (int tapi = 0; tapi < 4; tapi++) {
                int yy = ty[tapi], xx = tx[tapi];
                if ((unsigned)yy < HH && (unsigned)xx < WW) {
                    float4 xv =
                        *(const float4*)(xb + ((size_t)yy * WW + xx) * CC + lane * 4);
                    float w = tw[tapi];
                    acc[0] += w * xv.x;
                    acc[1] += w * xv.y;
                    acc[2] += w * xv.z;
                    acc[3] += w * xv.w;
                }
            }
            unsigned short h[4], l[4];
#pragma unroll
            for (int u = 0; u < 4; u++) {
                __nv_bfloat16 hb = __float2bfloat16(acc[u]);
                h[u] = __bfloat16_as_ushort(hb);
                l[u] = __bfloat16_as_ushort(
                    __float2bfloat16(acc[u] - __bfloat162float(hb)));
            }
            int o = p * KPAD + k * 64 + lane * 4;
            *(uint2*)&samp_hi[o] =
                make_uint2((uint32_t)h[0] | ((uint32_t)h[1] << 16),
                           (uint32_t)h[2] | ((uint32_t)h[3] << 16));
            *(uint2*)&samp_lo[o] =
                make_uint2((uint32_t)l[0] | ((uint32_t)l[1] << 16),
                           (uint32_t)l[2] | ((uint32_t)l[3] << 16));
        }
    }
    __syncthreads();

    // ---------------- Phase 2: tensor-core contraction ----------------
    int wid = tid >> 5, lane = tid & 31;
    int mt = wid >> 2;   // M-tile (pixels mt*16..+15)
    int nw = wid & 3;    // n8 pair {2nw, 2nw+1} -> outputs nw*16..+15
    int arow = mt * 16 + (lane & 15);
    int akoff = (lane >> 4) * 8;
    uint32_t aHbase = smem_u32(samp_hi) + (uint32_t)(arow * KPAD + akoff) * 2;
    uint32_t aLbase = smem_u32(samp_lo) + (uint32_t)(arow * KPAD + akoff) * 2;

    float d0[4] = {0.f, 0.f, 0.f, 0.f};  // n8 = 2nw
    float d1[4] = {0.f, 0.f, 0.f, 0.f};  // n8 = 2nw+1
    const uint2* wf = (const uint2*)g_wfrag;

#pragma unroll 4
    for (int k16 = 0; k16 < 36; k16++) {
        uint32_t aH[4], aL[4];
        ldmat4(aH, aHbase + k16 * 32);
        ldmat4(aL, aLbase + k16 * 32);
        int base = (k16 * 8 + nw * 2) * 2;
        uint2 bH0 = wf[(base + 0) * 32 + lane];
        uint2 bL0 = wf[(base + 1) * 32 + lane];
        uint2 bH1 = wf[(base + 2) * 32 + lane];
        uint2 bL1 = wf[(base + 3) * 32 + lane];
        mma16816(d0, aH, bH0);
        mma16816(d0, aH, bL0);
        mma16816(d0, aL, bH0);
        mma16816(d1, aH, bH1);
        mma16816(d1, aH, bL1);
        mma16816(d1, aL, bH1);
    }

    __syncthreads();  // samp fully consumed; reuse as f32 reduction buffer
    float* red = (float*)samp_hi;  // 32 px x 64 o = 8192 floats
    {
        int row = mt * 16 + (lane >> 2);
        int o0 = nw * 16 + (lane & 3) * 2;
        red[row * 64 + o0] = d0[0];
        red[row * 64 + o0 + 1] = d0[1];
        red[(row + 8) * 64 + o0] = d0[2];
        red[(row + 8) * 64 + o0 + 1] = d0[3];
        red[row * 64 + o0 + 8] = d1[0];
        red[row * 64 + o0 + 9] = d1[1];
        red[(row + 8) * 64 + o0 + 8] = d1[2];
        red[(row + 8) * 64 + o0 + 9] = d1[3];
    }
    __syncthreads();

    // coalesced NCHW store + bias
    for (int idx = tid; idx < 2048; idx += 256) {
        int oo = idx >> 5, p = idx & 31;
        float v = red[p * 64 + oo] + __ldg(&bias[oo]);
        out[((size_t)(b * OO + oo) * HH + i) * WW + j0 + p] = v;
    }
}

// ---------------------------------------------------------------------------
extern "C" void kernel_launch(void* const* d_in, const int* in_sizes, int n_in,
                              void* d_out, int out_size) {
    const float* x = (const float*)d_in[0];
    const float* weight = (const float*)d_in[1];
    const float* bias = (const float*)d_in[2];
    const float* off_w = (const float*)d_in[3];
    const float* off_b = (const float*)d_in[4];
    float* out = (float*)d_out;

    cudaFuncSetAttribute(k_main, cudaFuncAttributeMaxDynamicSharedMemorySize, SMEM_MAIN);

    k_transpose<<<dim3(BB * HH, WW / 32, CC / 32), dim3(32, 8)>>>(x);
    k_wfrag<<<(36 * 8 * 2 * 64 + 255) / 256, 256>>>(weight);
    k_off<<<dim3(WW / 16, HH / 64, BB), 256>>>(off_w, off_b);
    k_main<<<dim3(WW / 32, HH, BB), 256, SMEM_MAIN>>>(bias, out);
}

// round 10
// speedup vs baseline: 1.7343x; 1.7343x over previous
#include <cuda_runtime.h>
#include <cuda_bf16.h>
#include <cstdint>

// ---------------------------------------------------------------------------
// DeformableConv2d: B=8, C=64, H=W=128, O=64, K=3, stride=1, pad=1, dil=1
// Fully tensor-core: the offset-predictor conv is fused into k_main as a
// mini-GEMM on column-shifted NHWC rows (undeformed 3x3 conv), then the main
// contraction runs as in R7 (mma.sync m16n8k16, bf16 2-way split, fp32 accum).
// ---------------------------------------------------------------------------

#define BB 8
#define CC 64
#define HH 128
#define WW 128
#define OO 64
#define KPAD 584  // 576 + 8 pad (ushort); row stride 1168B, 16B-aligned
#define XRP 72    // xrow pad: 64 ch + 8 -> 144B row stride, conflict-free ldmatrix

// Scratch (static device globals; no runtime allocation)
__device__ float g_x[(size_t)BB * HH * WW * CC];  // x in NHWC
// main-weight fragments: [k16(36)][n8(8)][split(2)][lane(32)][reg(2)]
__device__ uint32_t g_wfrag[36 * 8 * 2 * 32 * 2];
// offset-weight fragments: [tap(9)][k16(4)][n8(3)][split(2)][lane(32)][reg(2)]
__device__ uint32_t g_wofrag[9 * 4 * 3 * 2 * 32 * 2];

// ---- tensor-core helpers ---------------------------------------------------
__device__ __forceinline__ void ldmat4(uint32_t* a, uint32_t addr) {
    asm volatile("ldmatrix.sync.aligned.m8n8.x4.shared.b16 {%0,%1,%2,%3}, [%4];"
                 : "=r"(a[0]), "=r"(a[1]), "=r"(a[2]), "=r"(a[3]) : "r"(addr));
}
__device__ __forceinline__ void mma16816(float* d, const uint32_t* a, uint2 b) {
    asm volatile(
        "mma.sync.aligned.m16n8k16.row.col.f32.bf16.bf16.f32 "
        "{%0,%1,%2,%3}, {%4,%5,%6,%7}, {%8,%9}, {%0,%1,%2,%3};"
        : "+f"(d[0]), "+f"(d[1]), "+f"(d[2]), "+f"(d[3])
        : "r"(a[0]), "r"(a[1]), "r"(a[2]), "r"(a[3]), "r"(b.x), "r"(b.y));
}
__device__ __forceinline__ uint32_t smem_u32(const void* p) {
    uint32_t a;
    asm("{ .reg .u64 t; cvta.to.shared.u64 t, %1; cvt.u32.u64 %0, t; }" : "=r"(a) : "l"(p));
    return a;
}
__device__ __forceinline__ void split_bf16(float v, unsigned short& h, unsigned short& l) {
    __nv_bfloat16 hb = __float2bfloat16(v);
    h = __bfloat16_as_ushort(hb);
    l = __bfloat16_as_ushort(__float2bfloat16(v - __bfloat162float(hb)));
}

// ---------------------------------------------------------------------------
// Kernel 1: NCHW -> NHWC transpose of x
// ---------------------------------------------------------------------------
__global__ void k_transpose(const float* __restrict__ x) {
    __shared__ float tile[32][33];
    int bh = blockIdx.x;
    int w0 = blockIdx.y * 32;
    int c0 = blockIdx.z * 32;
    int b = bh >> 7;
    const float* src = x + ((size_t)(b * CC) * HH + (bh & 127)) * WW;
#pragma unroll
    for (int i = 0; i < 32; i += 8) {
        int c = c0 + threadIdx.y + i;
        tile[threadIdx.y + i][threadIdx.x] = src[(size_t)c * HH * WW + w0 + threadIdx.x];
    }
    __syncthreads();
    float* dst = g_x + (size_t)bh * WW * CC;
#pragma unroll
    for (int i = 0; i < 32; i += 8) {
        int w = w0 + threadIdx.y + i;
        dst[(size_t)w * CC + c0 + threadIdx.x] = tile[threadIdx.x][threadIdx.y + i];
    }
}

// ---------------------------------------------------------------------------
// Kernel 2: main weight -> mma.sync B fragments (bf16 hi/lo).
// thread 'lane' reg r holds B[k0][n],B[k0+1][n]; k0=(lane&3)*2+r*8, n=n8*8+(lane>>2).
// K dim = tap*64 + c.
// ---------------------------------------------------------------------------
__global__ void k_wfrag(const float* __restrict__ w) {
    int idx = blockIdx.x * 256 + threadIdx.x;  // over 36864
    if (idx >= 36 * 8 * 2 * 64) return;
    int reg = idx & 1;
    int lane = (idx >> 1) & 31;
    int split = (idx >> 6) & 1;
    int n8 = (idx >> 7) & 7;
    int k16 = idx >> 10;
    int n = n8 * 8 + (lane >> 2);
    int k0 = (lane & 3) * 2 + reg * 8;
    int kg = k16 * 16 + k0;
    int tap = kg >> 6;
    int c = kg & 63;
    float v0 = w[(n * CC + c) * 9 + tap];
    float v1 = w[(n * CC + c + 1) * 9 + tap];
    unsigned short u0, u1, l0, l1;
    split_bf16(v0, u0, l0);
    split_bf16(v1, u1, l1);
    if (split) { u0 = l0; u1 = l1; }
    g_wfrag[idx] = (uint32_t)u0 | ((uint32_t)u1 << 16);
}

// ---------------------------------------------------------------------------
// Kernel 2b: offset weight (18,64,3,3) -> fragments, per-tap K chunks of 64.
// layout idx = ((((tap*4+k16)*3+n8)*2+split)*32+lane)*2+reg
// ---------------------------------------------------------------------------
__global__ void k_wofrag(const float* __restrict__ ow) {
    int idx = blockIdx.x * 256 + threadIdx.x;  // over 13824
    if (idx >= 9 * 4 * 3 * 2 * 64) return;
    int reg = idx & 1;
    int t = idx >> 1;
    int lane = t & 31;
    t >>= 5;
    int split = t & 1;
    t >>= 1;
    int n8 = t % 3;
    t /= 3;
    int k16 = t & 3;
    int tap = t >> 2;
    int n = n8 * 8 + (lane >> 2);
    int c = k16 * 16 + (lane & 3) * 2 + reg * 8;
    float v0 = 0.f, v1 = 0.f;
    if (n < 18) {
        v0 = ow[(n * CC + c) * 9 + tap];
        v1 = ow[(n * CC + c + 1) * 9 + tap];
    }
    unsigned short u0, u1, l0, l1;
    split_bf16(v0, u0, l0);
    split_bf16(v1, u1, l1);
    if (split) { u0 = l0; u1 = l1; }
    g_wofrag[idx] = (uint32_t)u0 | ((uint32_t)u1 << 16);
}

// ---------------------------------------------------------------------------
// Kernel 3: fused main kernel. grid (W/16, H, B), block 128.
// Stage A: stage x rows i-1..i+1 x 18 cols as bf16 hi/lo (overlaid on samp).
// Stage B: warps 0-2 compute the offset conv via mma (9 taps x 4 k16 x 3
//          products; A = column-shifted staged rows), +off_b -> offs[16][18].
// Stage C: bilinear gather (R7) -> samp_hi/lo[16][KPAD].
// Stage D: main contraction (R7): per warp 2 n8 tiles, 36 k16 x 6 MMAs.
// ---------------------------------------------------------------------------
__global__ __launch_bounds__(128) void k_main(const float* __restrict__ bias,
                                              const float* __restrict__ off_b,
                                              float* __restrict__ out) {
    __shared__ __align__(16) unsigned short samp_hi[16 * KPAD];  // 18688 B
    __shared__ __align__(16) unsigned short samp_lo[16 * KPAD];  // 18688 B
    __shared__ float offs[16][18];

    int tid = threadIdx.x;
    int b = blockIdx.z, i = blockIdx.y, j0 = blockIdx.x * 16;
    int wid = tid >> 5, lane = tid & 31;
    const float* xb = g_x + (size_t)b * HH * WW * CC;

    // ---- Stage A: x rows i-1..i+1, cols j0-1..j0+16, bf16 hi/lo, 144B rows ---
    unsigned short* xrowH = samp_hi;  // 3*18*72 = 3888 ushort (overlay)
    unsigned short* xrowL = samp_lo;
    for (int idx = tid; idx < 3 * 18 * 16; idx += 128) {
        int row = idx / 288;
        int rem = idx - row * 288;
        int col = rem >> 4, q = rem & 15;
        int y = i + row - 1, x = j0 + col - 1;
        float4 v = make_float4(0.f, 0.f, 0.f, 0.f);
        if ((unsigned)y < HH && (unsigned)x < WW)
            v = *(const float4*)(xb + ((size_t)y * WW + x) * CC + q * 4);
        float a[4] = {v.x, v.y, v.z, v.w};
        unsigned short h[4], l[4];
#pragma unroll
        for (int u = 0; u < 4; u++) split_bf16(a[u], h[u], l[u]);
        int o = (row * 18 + col) * XRP + q * 4;
        *(uint2*)&xrowH[o] = make_uint2((uint32_t)h[0] | ((uint32_t)h[1] << 16),
                                        (uint32_t)h[2] | ((uint32_t)h[3] << 16));
        *(uint2*)&xrowL[o] = make_uint2((uint32_t)l[0] | ((uint32_t)l[1] << 16),
                                        (uint32_t)l[2] | ((uint32_t)l[3] << 16));
    }
    __syncthreads();

    // ---- Stage B: offset conv via mma (warps 0..2, one n8 tile each) --------
    if (wid < 3) {
        float d[4] = {0.f, 0.f, 0.f, 0.f};
        uint32_t la = (uint32_t)((lane & 15) * XRP + (lane >> 4) * 8) * 2;
        uint32_t aH0 = smem_u32(xrowH) + la;
        uint32_t aL0 = smem_u32(xrowL) + la;
        const uint2* wf = (const uint2*)g_wofrag;
#pragma unroll 3
        for (int tap = 0; tap < 9; tap++) {
            int dy = tap / 3, dx = tap - dy * 3;
            uint32_t toff = (uint32_t)((dy * 18 + dx) * XRP) * 2;
#pragma unroll
            for (int k16 = 0; k16 < 4; k16++) {
                uint32_t aH[4], aL[4];
                ldmat4(aH, aH0 + toff + k16 * 32);
                ldmat4(aL, aL0 + toff + k16 * 32);
                int base = ((tap * 4 + k16) * 3 + wid) * 2;
                uint2 bH = wf[(base + 0) * 32 + lane];
                uint2 bL = wf[(base + 1) * 32 + lane];
                mma16816(d, aH, bH);
                mma16816(d, aH, bL);
                mma16816(d, aL, bH);
            }
        }
        int oc0 = wid * 8 + (lane & 3) * 2;
        int r0 = lane >> 2;
        if (oc0 + 1 < 18) {
            float b0 = __ldg(&off_b[oc0]), b1 = __ldg(&off_b[oc0 + 1]);
            offs[r0][oc0] = d[0] + b0;
            offs[r0][oc0 + 1] = d[1] + b1;
            offs[r0 + 8][oc0] = d[2] + b0;
            offs[r0 + 8][oc0 + 1] = d[3] + b1;
        }
    }
    __syncthreads();

    // ---- Stage C: bilinear gather -> bf16 hi/lo samp (overwrites xrow) ------
    {
        int g = tid >> 4, ln = tid & 15;
#pragma unroll 2
        for (int it = 0; it < 18; it++) {
            int pk = it * 8 + g;  // 0..143
            int p = pk / 9, k = pk - p * 9;
            float oy = offs[p][2 * k], ox = offs[p][2 * k + 1];
            float sy = (float)(i + k / 3) + oy;
            float sx = (float)(j0 + p + (k - (k / 3) * 3)) + ox;
            float fy = floorf(sy), fx = floorf(sx);
            float wy1 = sy - fy, wx1 = sx - fx;
            float wy0 = 1.f - wy1, wx0 = 1.f - wx1;
            int iy = (int)fy, ix = (int)fx;
            float tw[4] = {wy0 * wx0, wy0 * wx1, wy1 * wx0, wy1 * wx1};
            int ty[4] = {iy, iy, iy + 1, iy + 1};
            int tx[4] = {ix, ix + 1, ix, ix + 1};
            float acc[4] = {0.f, 0.f, 0.f, 0.f};
#pragma unroll
            for (int tapi = 0; tapi < 4; tapi++) {
                int yy = ty[tapi], xx = tx[tapi];
                if ((unsigned)yy < HH && (unsigned)xx < WW) {
                    float4 xv =
                        *(const float4*)(xb + ((size_t)yy * WW + xx) * CC + ln * 4);
                    float w = tw[tapi];
                    acc[0] += w * xv.x;
                    acc[1] += w * xv.y;
                    acc[2] += w * xv.z;
                    acc[3] += w * xv.w;
                }
            }
            unsigned short h[4], l[4];
#pragma unroll
            for (int u = 0; u < 4; u++) split_bf16(acc[u], h[u], l[u]);
            int o = p * KPAD + k * 64 + ln * 4;
            *(uint2*)&samp_hi[o] = make_uint2((uint32_t)h[0] | ((uint32_t)h[1] << 16),
                                              (uint32_t)h[2] | ((uint32_t)h[3] << 16));
            *(uint2*)&samp_lo[o] = make_uint2((uint32_t)l[0] | ((uint32_t)l[1] << 16),
                                              (uint32_t)l[2] | ((uint32_t)l[3] << 16));
        }
    }
    __syncthreads();

    // ---- Stage D: main tensor-core contraction ------------------------------
    int arow = lane & 15;
    int akoff = (lane >> 4) * 8;
    uint32_t aHbase = smem_u32(samp_hi) + (uint32_t)(arow * KPAD + akoff) * 2;
    uint32_t aLbase = smem_u32(samp_lo) + (uint32_t)(arow * KPAD + akoff) * 2;

    float d0[4] = {0.f, 0.f, 0.f, 0.f};  // n8 = wid*2
    float d1[4] = {0.f, 0.f, 0.f, 0.f};  // n8 = wid*2+1
    const uint2* wf = (const uint2*)g_wfrag;

#pragma unroll 4
    for (int k16 = 0; k16 < 36; k16++) {
        uint32_t aH[4], aL[4];
        ldmat4(aH, aHbase + k16 * 32);
        ldmat4(aL, aLbase + k16 * 32);
        int base = (k16 * 8 + wid * 2) * 2;
        uint2 bH0 = wf[(base + 0) * 32 + lane];
        uint2 bL0 = wf[(base + 1) * 32 + lane];
        uint2 bH1 = wf[(base + 2) * 32 + lane];
        uint2 bL1 = wf[(base + 3) * 32 + lane];
        mma16816(d0, aH, bH0);
        mma16816(d0, aH, bL0);
        mma16816(d0, aL, bH0);
        mma16816(d1, aH, bH1);
        mma16816(d1, aH, bL1);
        mma16816(d1, aL, bH1);
    }

    __syncthreads();  // samp fully consumed; reuse as f32 reduction buffer
    float* red = (float*)samp_hi;  // 16 px x 64 o = 4096 floats
    {
        int row = lane >> 2;
        int o0 = wid * 16 + (lane & 3) * 2;
        red[row * 64 + o0] = d0[0];
        red[row * 64 + o0 + 1] = d0[1];
        red[(row + 8) * 64 + o0] = d0[2];
        red[(row + 8) * 64 + o0 + 1] = d0[3];
        red[row * 64 + o0 + 8] = d1[0];
        red[row * 64 + o0 + 9] = d1[1];
        red[(row + 8) * 64 + o0 + 8] = d1[2];
        red[(row + 8) * 64 + o0 + 9] = d1[3];
    }
    __syncthreads();

    // coalesced NCHW store + bias
    for (int idx = tid; idx < 1024; idx += 128) {
        int oo = idx >> 4, p = idx & 15;
        float v = red[p * 64 + oo] + __ldg(&bias[oo]);
        out[((size_t)(b * OO + oo) * HH + i) * WW + j0 + p] = v;
    }
}

// ---------------------------------------------------------------------------
extern "C" void kernel_launch(void* const* d_in, const int* in_sizes, int n_in,
                              void* d_out, int out_size) {
    const float* x = (const float*)d_in[0];
    const float* weight = (const float*)d_in[1];
    const float* bias = (const float*)d_in[2];
    const float* off_w = (const float*)d_in[3];
    const float* off_b = (const float*)d_in[4];
    float* out = (float*)d_out;

    k_transpose<<<dim3(BB * HH, WW / 32, CC / 32), dim3(32, 8)>>>(x);
    k_wfrag<<<(36 * 8 * 2 * 64 + 255) / 256, 256>>>(weight);
    k_wofrag<<<(9 * 4 * 3 * 2 * 64 + 255) / 256, 256>>>(off_w);
    k_main<<<dim3(WW / 16, HH, BB), 128>>>(bias, off_b, out);
}

// round 11
// speedup vs baseline: 1.7911x; 1.0327x over previous
#include <cuda_runtime.h>
#include <cuda_bf16.h>
#include <cstdint>

// ---------------------------------------------------------------------------
// DeformableConv2d: B=8, C=64, H=W=128, O=64, K=3, stride=1, pad=1, dil=1
// Fully tensor-core: offset conv fused as mini-GEMM on column-shifted NHWC
// rows; main contraction = mma.sync m16n8k16, bf16 2-way split, fp32 accum.
// ---------------------------------------------------------------------------

#define BB 8
#define CC 64
#define HH 128
#define WW 128
#define OO 64
#define KPAD 584  // 576 + 8 pad (ushort); row stride 1168B, 16B-aligned
#define XRP 72    // xrow pad: 64 ch + 8 -> 144B row stride, conflict-free ldmatrix

// Scratch (static device globals; no runtime allocation)
__device__ float g_x[(size_t)BB * HH * WW * CC];  // x in NHWC
// main-weight fragments: [k16(36)][n8(8)][split(2)][lane(32)][reg(2)]
__device__ uint32_t g_wfrag[36 * 8 * 2 * 32 * 2];
// offset-weight fragments: [tap(9)][k16(4)][n8(3)][split(2)][lane(32)][reg(2)]
__device__ uint32_t g_wofrag[9 * 4 * 3 * 2 * 32 * 2];

// ---- tensor-core helpers ---------------------------------------------------
__device__ __forceinline__ void ldmat4(uint32_t* a, uint32_t addr) {
    asm volatile("ldmatrix.sync.aligned.m8n8.x4.shared.b16 {%0,%1,%2,%3}, [%4];"
                 : "=r"(a[0]), "=r"(a[1]), "=r"(a[2]), "=r"(a[3]) : "r"(addr));
}
__device__ __forceinline__ void mma16816(float* d, const uint32_t* a, uint2 b) {
    asm volatile(
        "mma.sync.aligned.m16n8k16.row.col.f32.bf16.bf16.f32 "
        "{%0,%1,%2,%3}, {%4,%5,%6,%7}, {%8,%9}, {%0,%1,%2,%3};"
        : "+f"(d[0]), "+f"(d[1]), "+f"(d[2]), "+f"(d[3])
        : "r"(a[0]), "r"(a[1]), "r"(a[2]), "r"(a[3]), "r"(b.x), "r"(b.y));
}
__device__ __forceinline__ uint32_t smem_u32(const void* p) {
    uint32_t a;
    asm("{ .reg .u64 t; cvta.to.shared.u64 t, %1; cvt.u32.u64 %0, t; }" : "=r"(a) : "l"(p));
    return a;
}
__device__ __forceinline__ void split_bf16(float v, unsigned short& h, unsigned short& l) {
    __nv_bfloat16 hb = __float2bfloat16(v);
    h = __bfloat16_as_ushort(hb);
    l = __bfloat16_as_ushort(__float2bfloat16(v - __bfloat162float(hb)));
}

// ---------------------------------------------------------------------------
// Kernel 1: NCHW -> NHWC transpose of x
// ---------------------------------------------------------------------------
__global__ void k_transpose(const float* __restrict__ x) {
    __shared__ float tile[32][33];
    int bh = blockIdx.x;
    int w0 = blockIdx.y * 32;
    int c0 = blockIdx.z * 32;
    int b = bh >> 7;
    const float* src = x + ((size_t)(b * CC) * HH + (bh & 127)) * WW;
#pragma unroll
    for (int i = 0; i < 32; i += 8) {
        int c = c0 + threadIdx.y + i;
        tile[threadIdx.y + i][threadIdx.x] = src[(size_t)c * HH * WW + w0 + threadIdx.x];
    }
    __syncthreads();
    float* dst = g_x + (size_t)bh * WW * CC;
#pragma unroll
    for (int i = 0; i < 32; i += 8) {
        int w = w0 + threadIdx.y + i;
        dst[(size_t)w * CC + c0 + threadIdx.x] = tile[threadIdx.x][threadIdx.y + i];
    }
}

// ---------------------------------------------------------------------------
// Kernel 2: main weight -> mma.sync B fragments (bf16 hi/lo).
// thread 'lane' reg r holds B[k0][n],B[k0+1][n]; k0=(lane&3)*2+r*8, n=n8*8+(lane>>2).
// ---------------------------------------------------------------------------
__global__ void k_wfrag(const float* __restrict__ w) {
    int idx = blockIdx.x * 256 + threadIdx.x;  // over 36864
    if (idx >= 36 * 8 * 2 * 64) return;
    int reg = idx & 1;
    int lane = (idx >> 1) & 31;
    int split = (idx >> 6) & 1;
    int n8 = (idx >> 7) & 7;
    int k16 = idx >> 10;
    int n = n8 * 8 + (lane >> 2);
    int k0 = (lane & 3) * 2 + reg * 8;
    int kg = k16 * 16 + k0;
    int tap = kg >> 6;
    int c = kg & 63;
    float v0 = w[(n * CC + c) * 9 + tap];
    float v1 = w[(n * CC + c + 1) * 9 + tap];
    unsigned short u0, u1, l0, l1;
    split_bf16(v0, u0, l0);
    split_bf16(v1, u1, l1);
    if (split) { u0 = l0; u1 = l1; }
    g_wfrag[idx] = (uint32_t)u0 | ((uint32_t)u1 << 16);
}

// ---------------------------------------------------------------------------
// Kernel 2b: offset weight (18,64,3,3) -> fragments, per-tap K chunks of 64.
// ---------------------------------------------------------------------------
__global__ void k_wofrag(const float* __restrict__ ow) {
    int idx = blockIdx.x * 256 + threadIdx.x;  // over 13824
    if (idx >= 9 * 4 * 3 * 2 * 64) return;
    int reg = idx & 1;
    int t = idx >> 1;
    int lane = t & 31;
    t >>= 5;
    int split = t & 1;
    t >>= 1;
    int n8 = t % 3;
    t /= 3;
    int k16 = t & 3;
    int tap = t >> 2;
    int n = n8 * 8 + (lane >> 2);
    int c = k16 * 16 + (lane & 3) * 2 + reg * 8;
    float v0 = 0.f, v1 = 0.f;
    if (n < 18) {
        v0 = ow[(n * CC + c) * 9 + tap];
        v1 = ow[(n * CC + c + 1) * 9 + tap];
    }
    unsigned short u0, u1, l0, l1;
    split_bf16(v0, u0, l0);
    split_bf16(v1, u1, l1);
    if (split) { u0 = l0; u1 = l1; }
    g_wofrag[idx] = (uint32_t)u0 | ((uint32_t)u1 << 16);
}

// ---------------------------------------------------------------------------
// Kernel 3: fused main kernel. grid (W/16, H, B), block 128, >=5 blocks/SM.
// Stage A: stage x rows i-1..i+1 x 18 cols as bf16 hi/lo (overlaid on samp).
// Stage B: warps 0-2: offset conv via mma -> offs[16][18] (+off_b).
// Stage C: bilinear gather, fully unrolled compile-time taps -> samp hi/lo.
// Stage D: main contraction: per warp 2 n8 tiles, 36 k16 x 6 MMAs.
// ---------------------------------------------------------------------------
__global__ __launch_bounds__(128, 5) void k_main(const float* __restrict__ bias,
                                                 const float* __restrict__ off_b,
                                                 float* __restrict__ out) {
    __shared__ __align__(16) unsigned short samp_hi[16 * KPAD];  // 18688 B
    __shared__ __align__(16) unsigned short samp_lo[16 * KPAD];  // 18688 B
    __shared__ float offs[16][18];

    int tid = threadIdx.x;
    int b = blockIdx.z, i = blockIdx.y, j0 = blockIdx.x * 16;
    int wid = tid >> 5, lane = tid & 31;
    const float* xb = g_x + (size_t)b * HH * WW * CC;

    // ---- Stage A: x rows i-1..i+1, cols j0-1..j0+16, bf16 hi/lo, 144B rows ---
    unsigned short* xrowH = samp_hi;  // 3*18*72 = 3888 ushort (overlay)
    unsigned short* xrowL = samp_lo;
    for (int idx = tid; idx < 3 * 18 * 16; idx += 128) {
        int row = idx / 288;
        int rem = idx - row * 288;
        int col = rem >> 4, q = rem & 15;
        int y = i + row - 1, x = j0 + col - 1;
        float4 v = make_float4(0.f, 0.f, 0.f, 0.f);
        if ((unsigned)y < HH && (unsigned)x < WW)
            v = *(const float4*)(xb + ((size_t)y * WW + x) * CC + q * 4);
        float a[4] = {v.x, v.y, v.z, v.w};
        unsigned short h[4], l[4];
#pragma unroll
        for (int u = 0; u < 4; u++) split_bf16(a[u], h[u], l[u]);
        int o = (row * 18 + col) * XRP + q * 4;
        *(uint2*)&xrowH[o] = make_uint2((uint32_t)h[0] | ((uint32_t)h[1] << 16),
                                        (uint32_t)h[2] | ((uint32_t)h[3] << 16));
        *(uint2*)&xrowL[o] = make_uint2((uint32_t)l[0] | ((uint32_t)l[1] << 16),
                                        (uint32_t)l[2] | ((uint32_t)l[3] << 16));
    }
    __syncthreads();

    // ---- Stage B: offset conv via mma (warps 0..2, one n8 tile each) --------
    if (wid < 3) {
        float d[4] = {0.f, 0.f, 0.f, 0.f};
        uint32_t la = (uint32_t)((lane & 15) * XRP + (lane >> 4) * 8) * 2;
        uint32_t aH0 = smem_u32(xrowH) + la;
        uint32_t aL0 = smem_u32(xrowL) + la;
        const uint2* wf = (const uint2*)g_wofrag;
#pragma unroll 3
        for (int tap = 0; tap < 9; tap++) {
            int dy = tap / 3, dx = tap - dy * 3;
            uint32_t toff = (uint32_t)((dy * 18 + dx) * XRP) * 2;
#pragma unroll
            for (int k16 = 0; k16 < 4; k16++) {
                uint32_t aH[4], aL[4];
                ldmat4(aH, aH0 + toff + k16 * 32);
                ldmat4(aL, aL0 + toff + k16 * 32);
                int base = ((tap * 4 + k16) * 3 + wid) * 2;
                uint2 bH = wf[(base + 0) * 32 + lane];
                uint2 bL = wf[(base + 1) * 32 + lane];
                mma16816(d, aH, bH);
                mma16816(d, aH, bL);
                mma16816(d, aL, bH);
            }
        }
        int oc0 = wid * 8 + (lane & 3) * 2;
        int r0 = lane >> 2;
        if (oc0 + 1 < 18) {
            float b0 = __ldg(&off_b[oc0]), b1 = __ldg(&off_b[oc0 + 1]);
            offs[r0][oc0] = d[0] + b0;
            offs[r0][oc0 + 1] = d[1] + b1;
            offs[r0 + 8][oc0] = d[2] + b0;
            offs[r0 + 8][oc0 + 1] = d[3] + b1;
        }
    }
    __syncthreads();

    // ---- Stage C: gather, compile-time taps (overwrites xrow overlay) -------
    {
        int g = tid >> 4, ln = tid & 15;
#pragma unroll
        for (int half = 0; half < 2; half++) {
            int p = g + 8 * half;
            const float* po = offs[p];
            float py = (float)i;
            float px = (float)(j0 + p);
            unsigned short* dsth = &samp_hi[p * KPAD + ln * 4];
            unsigned short* dstl = &samp_lo[p * KPAD + ln * 4];
#pragma unroll
            for (int k = 0; k < 9; k++) {          // k, k/3, k%3 fold to consts
                float oy = po[2 * k], ox = po[2 * k + 1];
                float sy = py + (float)(k / 3) + oy;
                float sx = px + (float)(k % 3) + ox;
                float fy = floorf(sy), fx = floorf(sx);
                float wy1 = sy - fy, wx1 = sx - fx;
                float wy0 = 1.f - wy1, wx0 = 1.f - wx1;
                int iy = (int)fy, ix = (int)fx;
                float tw0 = wy0 * wx0, tw1 = wy0 * wx1;
                float tw2 = wy1 * wx0, tw3 = wy1 * wx1;
                const float* r0 = xb + ((size_t)iy * WW + ix) * CC + ln * 4;
                float acc0 = 0.f, acc1 = 0.f, acc2 = 0.f, acc3 = 0.f;
                bool vy0 = (unsigned)iy < HH, vy1 = (unsigned)(iy + 1) < HH;
                bool vx0 = (unsigned)ix < WW, vx1 = (unsigned)(ix + 1) < WW;
                if (vy0 & vx0) {
                    float4 v = *(const float4*)r0;
                    acc0 += tw0 * v.x; acc1 += tw0 * v.y;
                    acc2 += tw0 * v.z; acc3 += tw0 * v.w;
                }
                if (vy0 & vx1) {
                    float4 v = *(const float4*)(r0 + CC);
                    acc0 += tw1 * v.x; acc1 += tw1 * v.y;
                    acc2 += tw1 * v.z; acc3 += tw1 * v.w;
                }
                if (vy1 & vx0) {
                    float4 v = *(const float4*)(r0 + WW * CC);
                    acc0 += tw2 * v.x; acc1 += tw2 * v.y;
                    acc2 += tw2 * v.z; acc3 += tw2 * v.w;
                }
                if (vy1 & vx1) {
                    float4 v = *(const float4*)(r0 + WW * CC + CC);
                    acc0 += tw3 * v.x; acc1 += tw3 * v.y;
                    acc2 += tw3 * v.z; acc3 += tw3 * v.w;
                }
                unsigned short h0, h1, h2, h3, l0, l1, l2, l3;
                split_bf16(acc0, h0, l0);
                split_bf16(acc1, h1, l1);
                split_bf16(acc2, h2, l2);
                split_bf16(acc3, h3, l3);
                *(uint2*)&dsth[k * 64] =
                    make_uint2((uint32_t)h0 | ((uint32_t)h1 << 16),
                               (uint32_t)h2 | ((uint32_t)h3 << 16));
                *(uint2*)&dstl[k * 64] =
                    make_uint2((uint32_t)l0 | ((uint32_t)l1 << 16),
                               (uint32_t)l2 | ((uint32_t)l3 << 16));
            }
        }
    }
    __syncthreads();

    // ---- Stage D: main tensor-core contraction ------------------------------
    int arow = lane & 15;
    int akoff = (lane >> 4) * 8;
    uint32_t aHbase = smem_u32(samp_hi) + (uint32_t)(arow * KPAD + akoff) * 2;
    uint32_t aLbase = smem_u32(samp_lo) + (uint32_t)(arow * KPAD + akoff) * 2;

    float d0[4] = {0.f, 0.f, 0.f, 0.f};  // n8 = wid*2
    float d1[4] = {0.f, 0.f, 0.f, 0.f};  // n8 = wid*2+1
    const uint2* wf = (const uint2*)g_wfrag;

#pragma unroll 6
    for (int k16 = 0; k16 < 36; k16++) {
        uint32_t aH[4], aL[4];
        ldmat4(aH, aHbase + k16 * 32);
        ldmat4(aL, aLbase + k16 * 32);
        int base = (k16 * 8 + wid * 2) * 2;
        uint2 bH0 = wf[(base + 0) * 32 + lane];
        uint2 bL0 = wf[(base + 1) * 32 + lane];
        uint2 bH1 = wf[(base + 2) * 32 + lane];
        uint2 bL1 = wf[(base + 3) * 32 + lane];
        mma16816(d0, aH, bH0);
        mma16816(d0, aH, bL0);
        mma16816(d0, aL, bH0);
        mma16816(d1, aH, bH1);
        mma16816(d1, aH, bL1);
        mma16816(d1, aL, bH1);
    }

    __syncthreads();  // samp fully consumed; reuse as f32 reduction buffer
    float* red = (float*)samp_hi;  // 16 px x 64 o = 4096 floats
    {
        int row = lane >> 2;
        int o0 = wid * 16 + (lane & 3) * 2;
        red[row * 64 + o0] = d0[0];
        red[row * 64 + o0 + 1] = d0[1];
        red[(row + 8) * 64 + o0] = d0[2];
        red[(row + 8) * 64 + o0 + 1] = d0[3];
        red[row * 64 + o0 + 8] = d1[0];
        red[row * 64 + o0 + 9] = d1[1];
        red[(row + 8) * 64 + o0 + 8] = d1[2];
        red[(row + 8) * 64 + o0 + 9] = d1[3];
    }
    __syncthreads();

    // coalesced NCHW store + bias
    for (int idx = tid; idx < 1024; idx += 128) {
        int oo = idx >> 4, p = idx & 15;
        float v = red[p * 64 + oo] + __ldg(&bias[oo]);
        out[((size_t)(b * OO + oo) * HH + i) * WW + j0 + p] = v;
    }
}

// ---------------------------------------------------------------------------
extern "C" void kernel_launch(void* const* d_in, const int* in_sizes, int n_in,
                              void* d_out, int out_size) {
    const float* x = (const float*)d_in[0];
    const float* weight = (const float*)d_in[1];
    const float* bias = (const float*)d_in[2];
    const float* off_w = (const float*)d_in[3];
    const float* off_b = (const float*)d_in[4];
    float* out = (float*)d_out;

    k_transpose<<<dim3(BB * HH, WW / 32, CC / 32), dim3(32, 8)>>>(x);
    k_wfrag<<<(36 * 8 * 2 * 64 + 255) / 256, 256>>>(weight);
    k_wofrag<<<(9 * 4 * 3 * 2 * 64 + 255) / 256, 256>>>(off_w);
    k_main<<<dim3(WW / 16, HH, BB), 128>>>(bias, off_b, out);
}

// round 12
// speedup vs baseline: 1.8319x; 1.0228x over previous
#include <cuda_runtime.h>
#include <cuda_bf16.h>
#include <cstdint>

// ---------------------------------------------------------------------------
// DeformableConv2d: B=8, C=64, H=W=128, O=64, K=3, stride=1, pad=1, dil=1
// Fully tensor-core: offset conv fused as mini-GEMM on column-shifted NHWC
// rows; main contraction = mma.sync m16n8k16, bf16 2-way split, fp32 accum.
// R11: 6 independent accumulator chains per warp in Stage D (was 2) to kill
// HMMA RAW-serialization; 3 chains in Stage B.
// ---------------------------------------------------------------------------

#define BB 8
#define CC 64
#define HH 128
#define WW 128
#define OO 64
#define KPAD 584  // 576 + 8 pad (ushort); row stride 1168B, 16B-aligned
#define XRP 72    // xrow pad: 64 ch + 8 -> 144B row stride, conflict-free ldmatrix

// Scratch (static device globals; no runtime allocation)
__device__ float g_x[(size_t)BB * HH * WW * CC];  // x in NHWC
// main-weight fragments: [k16(36)][n8(8)][split(2)][lane(32)][reg(2)]
__device__ uint32_t g_wfrag[36 * 8 * 2 * 32 * 2];
// offset-weight fragments: [tap(9)][k16(4)][n8(3)][split(2)][lane(32)][reg(2)]
__device__ uint32_t g_wofrag[9 * 4 * 3 * 2 * 32 * 2];

// ---- tensor-core helpers ---------------------------------------------------
__device__ __forceinline__ void ldmat4(uint32_t* a, uint32_t addr) {
    asm volatile("ldmatrix.sync.aligned.m8n8.x4.shared.b16 {%0,%1,%2,%3}, [%4];"
                 : "=r"(a[0]), "=r"(a[1]), "=r"(a[2]), "=r"(a[3]) : "r"(addr));
}
__device__ __forceinline__ void mma16816(float* d, const uint32_t* a, uint2 b) {
    asm volatile(
        "mma.sync.aligned.m16n8k16.row.col.f32.bf16.bf16.f32 "
        "{%0,%1,%2,%3}, {%4,%5,%6,%7}, {%8,%9}, {%0,%1,%2,%3};"
        : "+f"(d[0]), "+f"(d[1]), "+f"(d[2]), "+f"(d[3])
        : "r"(a[0]), "r"(a[1]), "r"(a[2]), "r"(a[3]), "r"(b.x), "r"(b.y));
}
__device__ __forceinline__ uint32_t smem_u32(const void* p) {
    uint32_t a;
    asm("{ .reg .u64 t; cvta.to.shared.u64 t, %1; cvt.u32.u64 %0, t; }" : "=r"(a) : "l"(p));
    return a;
}
__device__ __forceinline__ void split_bf16(float v, unsigned short& h, unsigned short& l) {
    __nv_bfloat16 hb = __float2bfloat16(v);
    h = __bfloat16_as_ushort(hb);
    l = __bfloat16_as_ushort(__float2bfloat16(v - __bfloat162float(hb)));
}

// ---------------------------------------------------------------------------
// Kernel 1: NCHW -> NHWC transpose of x
// ---------------------------------------------------------------------------
__global__ void k_transpose(const float* __restrict__ x) {
    __shared__ float tile[32][33];
    int bh = blockIdx.x;
    int w0 = blockIdx.y * 32;
    int c0 = blockIdx.z * 32;
    int b = bh >> 7;
    const float* src = x + ((size_t)(b * CC) * HH + (bh & 127)) * WW;
#pragma unroll
    for (int i = 0; i < 32; i += 8) {
        int c = c0 + threadIdx.y + i;
        tile[threadIdx.y + i][threadIdx.x] = src[(size_t)c * HH * WW + w0 + threadIdx.x];
    }
    __syncthreads();
    float* dst = g_x + (size_t)bh * WW * CC;
#pragma unroll
    for (int i = 0; i < 32; i += 8) {
        int w = w0 + threadIdx.y + i;
        dst[(size_t)w * CC + c0 + threadIdx.x] = tile[threadIdx.x][threadIdx.y + i];
    }
}

// ---------------------------------------------------------------------------
// Kernel 2: main weight -> mma.sync B fragments (bf16 hi/lo).
// ---------------------------------------------------------------------------
__global__ void k_wfrag(const float* __restrict__ w) {
    int idx = blockIdx.x * 256 + threadIdx.x;  // over 36864
    if (idx >= 36 * 8 * 2 * 64) return;
    int reg = idx & 1;
    int lane = (idx >> 1) & 31;
    int split = (idx >> 6) & 1;
    int n8 = (idx >> 7) & 7;
    int k16 = idx >> 10;
    int n = n8 * 8 + (lane >> 2);
    int k0 = (lane & 3) * 2 + reg * 8;
    int kg = k16 * 16 + k0;
    int tap = kg >> 6;
    int c = kg & 63;
    float v0 = w[(n * CC + c) * 9 + tap];
    float v1 = w[(n * CC + c + 1) * 9 + tap];
    unsigned short u0, u1, l0, l1;
    split_bf16(v0, u0, l0);
    split_bf16(v1, u1, l1);
    if (split) { u0 = l0; u1 = l1; }
    g_wfrag[idx] = (uint32_t)u0 | ((uint32_t)u1 << 16);
}

// ---------------------------------------------------------------------------
// Kernel 2b: offset weight (18,64,3,3) -> fragments, per-tap K chunks of 64.
// ---------------------------------------------------------------------------
__global__ void k_wofrag(const float* __restrict__ ow) {
    int idx = blockIdx.x * 256 + threadIdx.x;  // over 13824
    if (idx >= 9 * 4 * 3 * 2 * 64) return;
    int reg = idx & 1;
    int t = idx >> 1;
    int lane = t & 31;
    t >>= 5;
    int split = t & 1;
    t >>= 1;
    int n8 = t % 3;
    t /= 3;
    int k16 = t & 3;
    int tap = t >> 2;
    int n = n8 * 8 + (lane >> 2);
    int c = k16 * 16 + (lane & 3) * 2 + reg * 8;
    float v0 = 0.f, v1 = 0.f;
    if (n < 18) {
        v0 = ow[(n * CC + c) * 9 + tap];
        v1 = ow[(n * CC + c + 1) * 9 + tap];
    }
    unsigned short u0, u1, l0, l1;
    split_bf16(v0, u0, l0);
    split_bf16(v1, u1, l1);
    if (split) { u0 = l0; u1 = l1; }
    g_wofrag[idx] = (uint32_t)u0 | ((uint32_t)u1 << 16);
}

// ---------------------------------------------------------------------------
// Kernel 3: fused main kernel. grid (W/16, H, B), block 128, 5 blocks/SM.
// ---------------------------------------------------------------------------
__global__ __launch_bounds__(128, 5) void k_main(const float* __restrict__ bias,
                                                 const float* __restrict__ off_b,
                                                 float* __restrict__ out) {
    __shared__ __align__(16) unsigned short samp_hi[16 * KPAD];  // 18688 B
    __shared__ __align__(16) unsigned short samp_lo[16 * KPAD];  // 18688 B
    __shared__ float offs[16][18];

    int tid = threadIdx.x;
    int b = blockIdx.z, i = blockIdx.y, j0 = blockIdx.x * 16;
    int wid = tid >> 5, lane = tid & 31;
    const float* xb = g_x + (size_t)b * HH * WW * CC;

    // ---- Stage A: x rows i-1..i+1, cols j0-1..j0+16, bf16 hi/lo, 144B rows ---
    unsigned short* xrowH = samp_hi;  // 3*18*72 = 3888 ushort (overlay)
    unsigned short* xrowL = samp_lo;
    for (int idx = tid; idx < 3 * 18 * 16; idx += 128) {
        int row = idx / 288;
        int rem = idx - row * 288;
        int col = rem >> 4, q = rem & 15;
        int y = i + row - 1, x = j0 + col - 1;
        float4 v = make_float4(0.f, 0.f, 0.f, 0.f);
        if ((unsigned)y < HH && (unsigned)x < WW)
            v = *(const float4*)(xb + ((size_t)y * WW + x) * CC + q * 4);
        float a[4] = {v.x, v.y, v.z, v.w};
        unsigned short h[4], l[4];
#pragma unroll
        for (int u = 0; u < 4; u++) split_bf16(a[u], h[u], l[u]);
        int o = (row * 18 + col) * XRP + q * 4;
        *(uint2*)&xrowH[o] = make_uint2((uint32_t)h[0] | ((uint32_t)h[1] << 16),
                                        (uint32_t)h[2] | ((uint32_t)h[3] << 16));
        *(uint2*)&xrowL[o] = make_uint2((uint32_t)l[0] | ((uint32_t)l[1] << 16),
                                        (uint32_t)l[2] | ((uint32_t)l[3] << 16));
    }
    __syncthreads();

    // ---- Stage B: offset conv via mma (warps 0..2), 3 accumulator chains ----
    if (wid < 3) {
        float da[4] = {0.f, 0.f, 0.f, 0.f};
        float db[4] = {0.f, 0.f, 0.f, 0.f};
        float dc[4] = {0.f, 0.f, 0.f, 0.f};
        uint32_t la = (uint32_t)((lane & 15) * XRP + (lane >> 4) * 8) * 2;
        uint32_t aH0 = smem_u32(xrowH) + la;
        uint32_t aL0 = smem_u32(xrowL) + la;
        const uint2* wf = (const uint2*)g_wofrag;
#pragma unroll 3
        for (int tap = 0; tap < 9; tap++) {
            int dy = tap / 3, dx = tap - dy * 3;
            uint32_t toff = (uint32_t)((dy * 18 + dx) * XRP) * 2;
#pragma unroll
            for (int k16 = 0; k16 < 4; k16++) {
                uint32_t aH[4], aL[4];
                ldmat4(aH, aH0 + toff + k16 * 32);
                ldmat4(aL, aL0 + toff + k16 * 32);
                int base = ((tap * 4 + k16) * 3 + wid) * 2;
                uint2 bH = wf[(base + 0) * 32 + lane];
                uint2 bL = wf[(base + 1) * 32 + lane];
                mma16816(da, aH, bH);
                mma16816(db, aH, bL);
                mma16816(dc, aL, bH);
            }
        }
        int oc0 = wid * 8 + (lane & 3) * 2;
        int r0 = lane >> 2;
        if (oc0 + 1 < 18) {
            float b0 = __ldg(&off_b[oc0]), b1 = __ldg(&off_b[oc0 + 1]);
            offs[r0][oc0] = da[0] + db[0] + dc[0] + b0;
            offs[r0][oc0 + 1] = da[1] + db[1] + dc[1] + b1;
            offs[r0 + 8][oc0] = da[2] + db[2] + dc[2] + b0;
            offs[r0 + 8][oc0 + 1] = da[3] + db[3] + dc[3] + b1;
        }
    }
    __syncthreads();

    // ---- Stage C: gather, compile-time taps (overwrites xrow overlay) -------
    {
        int g = tid >> 4, ln = tid & 15;
#pragma unroll
        for (int half = 0; half < 2; half++) {
            int p = g + 8 * half;
            const float* po = offs[p];
            float py = (float)i;
            float px = (float)(j0 + p);
            unsigned short* dsth = &samp_hi[p * KPAD + ln * 4];
            unsigned short* dstl = &samp_lo[p * KPAD + ln * 4];
#pragma unroll
            for (int k = 0; k < 9; k++) {
                float oy = po[2 * k], ox = po[2 * k + 1];
                float sy = py + (float)(k / 3) + oy;
                float sx = px + (float)(k % 3) + ox;
                float fy = floorf(sy), fx = floorf(sx);
                float wy1 = sy - fy, wx1 = sx - fx;
                float wy0 = 1.f - wy1, wx0 = 1.f - wx1;
                int iy = (int)fy, ix = (int)fx;
                float tw0 = wy0 * wx0, tw1 = wy0 * wx1;
                float tw2 = wy1 * wx0, tw3 = wy1 * wx1;
                const float* r0 = xb + ((size_t)iy * WW + ix) * CC + ln * 4;
                float acc0 = 0.f, acc1 = 0.f, acc2 = 0.f, acc3 = 0.f;
                bool vy0 = (unsigned)iy < HH, vy1 = (unsigned)(iy + 1) < HH;
                bool vx0 = (unsigned)ix < WW, vx1 = (unsigned)(ix + 1) < WW;
                if (vy0 & vx0) {
                    float4 v = *(const float4*)r0;
                    acc0 += tw0 * v.x; acc1 += tw0 * v.y;
                    acc2 += tw0 * v.z; acc3 += tw0 * v.w;
                }
                if (vy0 & vx1) {
                    float4 v = *(const float4*)(r0 + CC);
                    acc0 += tw1 * v.x; acc1 += tw1 * v.y;
                    acc2 += tw1 * v.z; acc3 += tw1 * v.w;
                }
                if (vy1 & vx0) {
                    float4 v = *(const float4*)(r0 + WW * CC);
                    acc0 += tw2 * v.x; acc1 += tw2 * v.y;
                    acc2 += tw2 * v.z; acc3 += tw2 * v.w;
                }
                if (vy1 & vx1) {
                    float4 v = *(const float4*)(r0 + WW * CC + CC);
                    acc0 += tw3 * v.x; acc1 += tw3 * v.y;
                    acc2 += tw3 * v.z; acc3 += tw3 * v.w;
                }
                unsigned short h0, h1, h2, h3, l0, l1, l2, l3;
                split_bf16(acc0, h0, l0);
                split_bf16(acc1, h1, l1);
                split_bf16(acc2, h2, l2);
                split_bf16(acc3, h3, l3);
                *(uint2*)&dsth[k * 64] =
                    make_uint2((uint32_t)h0 | ((uint32_t)h1 << 16),
                               (uint32_t)h2 | ((uint32_t)h3 << 16));
                *(uint2*)&dstl[k * 64] =
                    make_uint2((uint32_t)l0 | ((uint32_t)l1 << 16),
                               (uint32_t)l2 | ((uint32_t)l3 << 16));
            }
        }
    }
    __syncthreads();

    // ---- Stage D: main contraction, 6 independent accumulator chains --------
    int arow = lane & 15;
    int akoff = (lane >> 4) * 8;
    uint32_t aHbase = smem_u32(samp_hi) + (uint32_t)(arow * KPAD + akoff) * 2;
    uint32_t aLbase = smem_u32(samp_lo) + (uint32_t)(arow * KPAD + akoff) * 2;

    float d0h[4] = {0.f, 0.f, 0.f, 0.f};  // n8=2wid,   Ahi*Whi
    float d0l[4] = {0.f, 0.f, 0.f, 0.f};  // n8=2wid,   Ahi*Wlo
    float d0x[4] = {0.f, 0.f, 0.f, 0.f};  // n8=2wid,   Alo*Whi
    float d1h[4] = {0.f, 0.f, 0.f, 0.f};  // n8=2wid+1, Ahi*Whi
    float d1l[4] = {0.f, 0.f, 0.f, 0.f};  // n8=2wid+1, Ahi*Wlo
    float d1x[4] = {0.f, 0.f, 0.f, 0.f};  // n8=2wid+1, Alo*Whi
    const uint2* wf = (const uint2*)g_wfrag;

#pragma unroll 6
    for (int k16 = 0; k16 < 36; k16++) {
        uint32_t aH[4], aL[4];
        ldmat4(aH, aHbase + k16 * 32);
        ldmat4(aL, aLbase + k16 * 32);
        int base = (k16 * 8 + wid * 2) * 2;
        uint2 bH0 = wf[(base + 0) * 32 + lane];
        uint2 bL0 = wf[(base + 1) * 32 + lane];
        uint2 bH1 = wf[(base + 2) * 32 + lane];
        uint2 bL1 = wf[(base + 3) * 32 + lane];
        mma16816(d0h, aH, bH0);
        mma16816(d0l, aH, bL0);
        mma16816(d0x, aL, bH0);
        mma16816(d1h, aH, bH1);
        mma16816(d1l, aH, bL1);
        mma16816(d1x, aL, bH1);
    }

    __syncthreads();  // samp fully consumed; reuse as f32 reduction buffer
    float* red = (float*)samp_hi;  // 16 px x 64 o = 4096 floats
    {
        int row = lane >> 2;
        int o0 = wid * 16 + (lane & 3) * 2;
        red[row * 64 + o0] = d0h[0] + d0l[0] + d0x[0];
        red[row * 64 + o0 + 1] = d0h[1] + d0l[1] + d0x[1];
        red[(row + 8) * 64 + o0] = d0h[2] + d0l[2] + d0x[2];
        red[(row + 8) * 64 + o0 + 1] = d0h[3] + d0l[3] + d0x[3];
        red[row * 64 + o0 + 8] = d1h[0] + d1l[0] + d1x[0];
        red[row * 64 + o0 + 9] = d1h[1] + d1l[1] + d1x[1];
        red[(row + 8) * 64 + o0 + 8] = d1h[2] + d1l[2] + d1x[2];
        red[(row + 8) * 64 + o0 + 9] = d1h[3] + d1l[3] + d1x[3];
    }
    __syncthreads();

    // coalesced NCHW store + bias
    for (int idx = tid; idx < 1024; idx += 128) {
        int oo = idx >> 4, p = idx & 15;
        float v = red[p * 64 + oo] + __ldg(&bias[oo]);
        out[((size_t)(b * OO + oo) * HH + i) * WW + j0 + p] = v;
    }
}

// ---------------------------------------------------------------------------
extern "C" void kernel_launch(void* const* d_in, const int* in_sizes, int n_in,
                              void* d_out, int out_size) {
    const float* x = (const float*)d_in[0];
    const float* weight = (const float*)d_in[1];
    const float* bias = (const float*)d_in[2];
    const float* off_w = (const float*)d_in[3];
    const float* off_b = (const float*)d_in[4];
    float* out = (float*)d_out;

    k_transpose<<<dim3(BB * HH, WW / 32, CC / 32), dim3(32, 8)>>>(x);
    k_wfrag<<<(36 * 8 * 2 * 64 + 255) / 256, 256>>>(weight);
    k_wofrag<<<(9 * 4 * 3 * 2 * 64 + 255) / 256, 256>>>(off_w);
    k_main<<<dim3(WW / 16, HH, BB), 128>>>(bias, off_b, out);
}

// round 13
// speedup vs baseline: 2.3087x; 1.2603x over previous
#include <cuda_runtime.h>
#include <cuda_fp16.h>
#include <cstdint>

// ---------------------------------------------------------------------------
// DeformableConv2d: B=8, C=64, H=W=128, O=64, K=3, stride=1, pad=1, dil=1
// Fully tensor-core. R12: all-fp16 operands — A single fp16 (eps 2^-11),
// W split fp16 hi/lo (W error ~2^-22) -> per-product err ~2^-12, output
// rel_err ~1.5e-4 << 1e-3. Removes samp_lo, 1/2 of A-ldmatrix, 1/3 of MMAs.
// ---------------------------------------------------------------------------

#define BB 8
#define CC 64
#define HH 128
#define WW 128
#define OO 64
#define KPAD 584  // 576 + 8 pad (ushort); row stride 1168B, 16B-aligned
#define XRP 72    // xrow pad: 64 ch + 8 -> 144B row stride, conflict-free ldmatrix

// Scratch (static device globals; no runtime allocation)
__device__ float g_x[(size_t)BB * HH * WW * CC];  // x in NHWC
// main-weight fragments: [k16(36)][n8(8)][split(2)][lane(32)][reg(2)]
__device__ uint32_t g_wfrag[36 * 8 * 2 * 32 * 2];
// offset-weight fragments: [tap(9)][k16(4)][n8(3)][split(2)][lane(32)][reg(2)]
__device__ uint32_t g_wofrag[9 * 4 * 3 * 2 * 32 * 2];

// ---- tensor-core helpers ---------------------------------------------------
__device__ __forceinline__ void ldmat4(uint32_t* a, uint32_t addr) {
    asm volatile("ldmatrix.sync.aligned.m8n8.x4.shared.b16 {%0,%1,%2,%3}, [%4];"
                 : "=r"(a[0]), "=r"(a[1]), "=r"(a[2]), "=r"(a[3]) : "r"(addr));
}
__device__ __forceinline__ void mma16816(float* d, const uint32_t* a, uint2 b) {
    asm volatile(
        "mma.sync.aligned.m16n8k16.row.col.f32.f16.f16.f32 "
        "{%0,%1,%2,%3}, {%4,%5,%6,%7}, {%8,%9}, {%0,%1,%2,%3};"
        : "+f"(d[0]), "+f"(d[1]), "+f"(d[2]), "+f"(d[3])
        : "r"(a[0]), "r"(a[1]), "r"(a[2]), "r"(a[3]), "r"(b.x), "r"(b.y));
}
__device__ __forceinline__ uint32_t smem_u32(const void* p) {
    uint32_t a;
    asm("{ .reg .u64 t; cvta.to.shared.u64 t, %1; cvt.u32.u64 %0, t; }" : "=r"(a) : "l"(p));
    return a;
}
// fp16 split: h = fp16(v), l = fp16(v - h)
__device__ __forceinline__ void split_f16(float v, unsigned short& h, unsigned short& l) {
    __half hb = __float2half_rn(v);
    h = __half_as_ushort(hb);
    l = __half_as_ushort(__float2half_rn(v - __half2float(hb)));
}
__device__ __forceinline__ unsigned short f16(float v) {
    return __half_as_ushort(__float2half_rn(v));
}

// ---------------------------------------------------------------------------
// Kernel 1: NCHW -> NHWC transpose of x
// ---------------------------------------------------------------------------
__global__ void k_transpose(const float* __restrict__ x) {
    __shared__ float tile[32][33];
    int bh = blockIdx.x;
    int w0 = blockIdx.y * 32;
    int c0 = blockIdx.z * 32;
    int b = bh >> 7;
    const float* src = x + ((size_t)(b * CC) * HH + (bh & 127)) * WW;
#pragma unroll
    for (int i = 0; i < 32; i += 8) {
        int c = c0 + threadIdx.y + i;
        tile[threadIdx.y + i][threadIdx.x] = src[(size_t)c * HH * WW + w0 + threadIdx.x];
    }
    __syncthreads();
    float* dst = g_x + (size_t)bh * WW * CC;
#pragma unroll
    for (int i = 0; i < 32; i += 8) {
        int w = w0 + threadIdx.y + i;
        dst[(size_t)w * CC + c0 + threadIdx.x] = tile[threadIdx.x][threadIdx.y + i];
    }
}

// ---------------------------------------------------------------------------
// Kernel 2: main weight -> mma.sync B fragments (fp16 hi/lo).
// thread 'lane' reg r holds B[k0][n],B[k0+1][n]; k0=(lane&3)*2+r*8, n=n8*8+(lane>>2).
// ---------------------------------------------------------------------------
__global__ void k_wfrag(const float* __restrict__ w) {
    int idx = blockIdx.x * 256 + threadIdx.x;  // over 36864
    if (idx >= 36 * 8 * 2 * 64) return;
    int reg = idx & 1;
    int lane = (idx >> 1) & 31;
    int split = (idx >> 6) & 1;
    int n8 = (idx >> 7) & 7;
    int k16 = idx >> 10;
    int n = n8 * 8 + (lane >> 2);
    int k0 = (lane & 3) * 2 + reg * 8;
    int kg = k16 * 16 + k0;
    int tap = kg >> 6;
    int c = kg & 63;
    float v0 = w[(n * CC + c) * 9 + tap];
    float v1 = w[(n * CC + c + 1) * 9 + tap];
    unsigned short u0, u1, l0, l1;
    split_f16(v0, u0, l0);
    split_f16(v1, u1, l1);
    if (split) { u0 = l0; u1 = l1; }
    g_wfrag[idx] = (uint32_t)u0 | ((uint32_t)u1 << 16);
}

// ---------------------------------------------------------------------------
// Kernel 2b: offset weight (18,64,3,3) -> fragments, per-tap K chunks of 64.
// ---------------------------------------------------------------------------
__global__ void k_wofrag(const float* __restrict__ ow) {
    int idx = blockIdx.x * 256 + threadIdx.x;  // over 13824
    if (idx >= 9 * 4 * 3 * 2 * 64) return;
    int reg = idx & 1;
    int t = idx >> 1;
    int lane = t & 31;
    t >>= 5;
    int split = t & 1;
    t >>= 1;
    int n8 = t % 3;
    t /= 3;
    int k16 = t & 3;
    int tap = t >> 2;
    int n = n8 * 8 + (lane >> 2);
    int c = k16 * 16 + (lane & 3) * 2 + reg * 8;
    float v0 = 0.f, v1 = 0.f;
    if (n < 18) {
        v0 = ow[(n * CC + c) * 9 + tap];
        v1 = ow[(n * CC + c + 1) * 9 + tap];
    }
    unsigned short u0, u1, l0, l1;
    split_f16(v0, u0, l0);
    split_f16(v1, u1, l1);
    if (split) { u0 = l0; u1 = l1; }
    g_wofrag[idx] = (uint32_t)u0 | ((uint32_t)u1 << 16);
}

// ---------------------------------------------------------------------------
// Kernel 3: fused main kernel. grid (W/16, H, B), block 128, 6 blocks/SM.
// Stage A: x rows i-1..i+1 x 18 cols -> fp16 (overlay on samp).
// Stage B: warps 0-2: offset conv via mma (A single, W hi/lo: 2 MMAs/k16).
// Stage C: bilinear gather -> fp16 samp[16][KPAD].
// Stage D: main contraction: per warp 2 n8 tiles, 36 k16 x 4 MMAs.
// ---------------------------------------------------------------------------
__global__ __launch_bounds__(128, 6) void k_main(const float* __restrict__ bias,
                                                 const float* __restrict__ off_b,
                                                 float* __restrict__ out) {
    __shared__ __align__(16) unsigned short samp[16 * KPAD];  // 18688 B
    __shared__ float offs[16][18];

    int tid = threadIdx.x;
    int b = blockIdx.z, i = blockIdx.y, j0 = blockIdx.x * 16;
    int wid = tid >> 5, lane = tid & 31;
    const float* xb = g_x + (size_t)b * HH * WW * CC;

    // ---- Stage A: x rows i-1..i+1, cols j0-1..j0+16, fp16, 144B rows --------
    unsigned short* xrow = samp;  // 3*18*72 = 3888 ushort (overlay)
    for (int idx = tid; idx < 3 * 18 * 16; idx += 128) {
        int row = idx / 288;
        int rem = idx - row * 288;
        int col = rem >> 4, q = rem & 15;
        int y = i + row - 1, x = j0 + col - 1;
        float4 v = make_float4(0.f, 0.f, 0.f, 0.f);
        if ((unsigned)y < HH && (unsigned)x < WW)
            v = *(const float4*)(xb + ((size_t)y * WW + x) * CC + q * 4);
        int o = (row * 18 + col) * XRP + q * 4;
        *(uint2*)&xrow[o] =
            make_uint2((uint32_t)f16(v.x) | ((uint32_t)f16(v.y) << 16),
                       (uint32_t)f16(v.z) | ((uint32_t)f16(v.w) << 16));
    }
    __syncthreads();

    // ---- Stage B: offset conv via mma (warps 0..2), A single + W hi/lo ------
    if (wid < 3) {
        float da[4] = {0.f, 0.f, 0.f, 0.f};
        float db[4] = {0.f, 0.f, 0.f, 0.f};
        uint32_t la = (uint32_t)((lane & 15) * XRP + (lane >> 4) * 8) * 2;
        uint32_t aB0 = smem_u32(xrow) + la;
        const uint2* wf = (const uint2*)g_wofrag;
#pragma unroll 3
        for (int tap = 0; tap < 9; tap++) {
            int dy = tap / 3, dx = tap - dy * 3;
            uint32_t toff = (uint32_t)((dy * 18 + dx) * XRP) * 2;
#pragma unroll
            for (int k16 = 0; k16 < 4; k16++) {
                uint32_t aA[4];
                ldmat4(aA, aB0 + toff + k16 * 32);
                int base = ((tap * 4 + k16) * 3 + wid) * 2;
                uint2 bH = wf[(base + 0) * 32 + lane];
                uint2 bL = wf[(base + 1) * 32 + lane];
                mma16816(da, aA, bH);
                mma16816(db, aA, bL);
            }
        }
        int oc0 = wid * 8 + (lane & 3) * 2;
        int r0 = lane >> 2;
        if (oc0 + 1 < 18) {
            float b0 = __ldg(&off_b[oc0]), b1 = __ldg(&off_b[oc0 + 1]);
            offs[r0][oc0] = da[0] + db[0] + b0;
            offs[r0][oc0 + 1] = da[1] + db[1] + b1;
            offs[r0 + 8][oc0] = da[2] + db[2] + b0;
            offs[r0 + 8][oc0 + 1] = da[3] + db[3] + b1;
        }
    }
    __syncthreads();

    // ---- Stage C: gather, compile-time taps -> fp16 samp --------------------
    {
        int g = tid >> 4, ln = tid & 15;
#pragma unroll
        for (int half = 0; half < 2; half++) {
            int p = g + 8 * half;
            const float* po = offs[p];
            float py = (float)i;
            float px = (float)(j0 + p);
            unsigned short* dst = &samp[p * KPAD + ln * 4];
#pragma unroll
            for (int k = 0; k < 9; k++) {
                float oy = po[2 * k], ox = po[2 * k + 1];
                float sy = py + (float)(k / 3) + oy;
                float sx = px + (float)(k % 3) + ox;
                float fy = floorf(sy), fx = floorf(sx);
                float wy1 = sy - fy, wx1 = sx - fx;
                float wy0 = 1.f - wy1, wx0 = 1.f - wx1;
                int iy = (int)fy, ix = (int)fx;
                float tw0 = wy0 * wx0, tw1 = wy0 * wx1;
                float tw2 = wy1 * wx0, tw3 = wy1 * wx1;
                const float* r0 = xb + ((size_t)iy * WW + ix) * CC + ln * 4;
                float acc0 = 0.f, acc1 = 0.f, acc2 = 0.f, acc3 = 0.f;
                bool vy0 = (unsigned)iy < HH, vy1 = (unsigned)(iy + 1) < HH;
                bool vx0 = (unsigned)ix < WW, vx1 = (unsigned)(ix + 1) < WW;
                if (vy0 & vx0) {
                    float4 v = *(const float4*)r0;
                    acc0 += tw0 * v.x; acc1 += tw0 * v.y;
                    acc2 += tw0 * v.z; acc3 += tw0 * v.w;
                }
                if (vy0 & vx1) {
                    float4 v = *(const float4*)(r0 + CC);
                    acc0 += tw1 * v.x; acc1 += tw1 * v.y;
                    acc2 += tw1 * v.z; acc3 += tw1 * v.w;
                }
                if (vy1 & vx0) {
                    float4 v = *(const float4*)(r0 + WW * CC);
                    acc0 += tw2 * v.x; acc1 += tw2 * v.y;
                    acc2 += tw2 * v.z; acc3 += tw2 * v.w;
                }
                if (vy1 & vx1) {
                    float4 v = *(const float4*)(r0 + WW * CC + CC);
                    acc0 += tw3 * v.x; acc1 += tw3 * v.y;
                    acc2 += tw3 * v.z; acc3 += tw3 * v.w;
                }
                *(uint2*)&dst[k * 64] =
                    make_uint2((uint32_t)f16(acc0) | ((uint32_t)f16(acc1) << 16),
                               (uint32_t)f16(acc2) | ((uint32_t)f16(acc3) << 16));
            }
        }
    }
    __syncthreads();

    // ---- Stage D: main contraction, A single fp16, W hi/lo: 4 MMAs/k16 ------
    int arow = lane & 15;
    int akoff = (lane >> 4) * 8;
    uint32_t aBase = smem_u32(samp) + (uint32_t)(arow * KPAD + akoff) * 2;

    float d0h[4] = {0.f, 0.f, 0.f, 0.f};  // n8=2wid,   A*Whi
    float d0l[4] = {0.f, 0.f, 0.f, 0.f};  // n8=2wid,   A*Wlo
    float d1h[4] = {0.f, 0.f, 0.f, 0.f};  // n8=2wid+1, A*Whi
    float d1l[4] = {0.f, 0.f, 0.f, 0.f};  // n8=2wid+1, A*Wlo
    const uint2* wf = (const uint2*)g_wfrag;

#pragma unroll 6
    for (int k16 = 0; k16 < 36; k16++) {
        uint32_t aA[4];
        ldmat4(aA, aBase + k16 * 32);
        int base = (k16 * 8 + wid * 2) * 2;
        uint2 bH0 = wf[(base + 0) * 32 + lane];
        uint2 bL0 = wf[(base + 1) * 32 + lane];
        uint2 bH1 = wf[(base + 2) * 32 + lane];
        uint2 bL1 = wf[(base + 3) * 32 + lane];
        mma16816(d0h, aA, bH0);
        mma16816(d0l, aA, bL0);
        mma16816(d1h, aA, bH1);
        mma16816(d1l, aA, bL1);
    }

    __syncthreads();  // samp fully consumed; reuse as f32 reduction buffer
    float* red = (float*)samp;  // 16 px x 64 o = 4096 floats (16 KB, fits)
    {
        int row = lane >> 2;
        int o0 = wid * 16 + (lane & 3) * 2;
        red[row * 64 + o0] = d0h[0] + d0l[0];
        red[row * 64 + o0 + 1] = d0h[1] + d0l[1];
        red[(row + 8) * 64 + o0] = d0h[2] + d0l[2];
        red[(row + 8) * 64 + o0 + 1] = d0h[3] + d0l[3];
        red[row * 64 + o0 + 8] = d1h[0] + d1l[0];
        red[row * 64 + o0 + 9] = d1h[1] + d1l[1];
        red[(row + 8) * 64 + o0 + 8] = d1h[2] + d1l[2];
        red[(row + 8) * 64 + o0 + 9] = d1h[3] + d1l[3];
    }
    __syncthreads();

    // coalesced NCHW store + bias
    for (int idx = tid; idx < 1024; idx += 128) {
        int oo = idx >> 4, p = idx & 15;
        float v = red[p * 64 + oo] + __ldg(&bias[oo]);
        out[((size_t)(b * OO + oo) * HH + i) * WW + j0 + p] = v;
    }
}

// ---------------------------------------------------------------------------
extern "C" void kernel_launch(void* const* d_in, const int* in_sizes, int n_in,
                              void* d_out, int out_size) {
    const float* x = (const float*)d_in[0];
    const float* weight = (const float*)d_in[1];
    const float* bias = (const float*)d_in[2];
    const float* off_w = (const float*)d_in[3];
    const float* off_b = (const float*)d_in[4];
    float* out = (float*)d_out;

    k_transpose<<<dim3(BB * HH, WW / 32, CC / 32), dim3(32, 8)>>>(x);
    k_wfrag<<<(36 * 8 * 2 * 64 + 255) / 256, 256>>>(weight);
    k_wofrag<<<(9 * 4 * 3 * 2 * 64 + 255) / 256, 256>>>(off_w);
    k_main<<<dim3(WW / 16, HH, BB), 128>>>(bias, off_b, out);
}

// round 15
// speedup vs baseline: 2.7506x; 1.1914x over previous
#include <cuda_runtime.h>
#include <cuda_fp16.h>
#include <cstdint>

// ---------------------------------------------------------------------------
// DeformableConv2d: B=8, C=64, H=W=128, O=64, K=3, stride=1, pad=1, dil=1
// Fully tensor-core, all-fp16 operands (A and W single fp16, fp32 accum).
// Error: per-term ~2^-11 rms x random-sign sum -> output rel_err ~3.5e-4.
// ---------------------------------------------------------------------------

#define BB 8
#define CC 64
#define HH 128
#define WW 128
#define OO 64
#define KPAD 584  // 576 + 8 pad (ushort); row stride 1168B, 16B-aligned
#define XRP 72    // xrow pad: 64 ch + 8 -> 144B row stride, conflict-free ldmatrix

// Scratch (static device globals; no runtime allocation)
__device__ float g_x[(size_t)BB * HH * WW * CC];  // x in NHWC
// main-weight fragments: [k16(36)][n8(8)][lane(32)][reg(2)]
__device__ uint32_t g_wfrag[36 * 8 * 32 * 2];
// offset-weight fragments: [tap(9)][k16(4)][n8(3)][lane(32)][reg(2)]
__device__ uint32_t g_wofrag[9 * 4 * 3 * 32 * 2];

// ---- tensor-core helpers ---------------------------------------------------
__device__ __forceinline__ void ldmat4(uint32_t* a, uint32_t addr) {
    asm volatile("ldmatrix.sync.aligned.m8n8.x4.shared.b16 {%0,%1,%2,%3}, [%4];"
                 : "=r"(a[0]), "=r"(a[1]), "=r"(a[2]), "=r"(a[3]) : "r"(addr));
}
__device__ __forceinline__ void mma16816(float* d, const uint32_t* a, uint2 b) {
    asm volatile(
        "mma.sync.aligned.m16n8k16.row.col.f32.f16.f16.f32 "
        "{%0,%1,%2,%3}, {%4,%5,%6,%7}, {%8,%9}, {%0,%1,%2,%3};"
        : "+f"(d[0]), "+f"(d[1]), "+f"(d[2]), "+f"(d[3])
        : "r"(a[0]), "r"(a[1]), "r"(a[2]), "r"(a[3]), "r"(b.x), "r"(b.y));
}
__device__ __forceinline__ uint32_t smem_u32(const void* p) {
    uint32_t a;
    asm("{ .reg .u64 t; cvta.to.shared.u64 t, %1; cvt.u32.u64 %0, t; }" : "=r"(a) : "l"(p));
    return a;
}
__device__ __forceinline__ unsigned short f16(float v) {
    return __half_as_ushort(__float2half_rn(v));
}

// ---------------------------------------------------------------------------
// Kernel 1: NCHW -> NHWC transpose of x
// ---------------------------------------------------------------------------
__global__ void k_transpose(const float* __restrict__ x) {
    __shared__ float tile[32][33];
    int bh = blockIdx.x;
    int w0 = blockIdx.y * 32;
    int c0 = blockIdx.z * 32;
    int b = bh >> 7;
    const float* src = x + ((size_t)(b * CC) * HH + (bh & 127)) * WW;
#pragma unroll
    for (int i = 0; i < 32; i += 8) {
        int c = c0 + threadIdx.y + i;
        tile[threadIdx.y + i][threadIdx.x] = src[(size_t)c * HH * WW + w0 + threadIdx.x];
    }
    __syncthreads();
    float* dst = g_x + (size_t)bh * WW * CC;
#pragma unroll
    for (int i = 0; i < 32; i += 8) {
        int w = w0 + threadIdx.y + i;
        dst[(size_t)w * CC + c0 + threadIdx.x] = tile[threadIdx.x][threadIdx.y + i];
    }
}

// ---------------------------------------------------------------------------
// Kernel 2: main weight -> mma.sync B fragments (single fp16).
// thread 'lane' reg r holds B[k0][n],B[k0+1][n]; k0=(lane&3)*2+r*8, n=n8*8+(lane>>2).
// ---------------------------------------------------------------------------
__global__ void k_wfrag(const float* __restrict__ w) {
    int idx = blockIdx.x * 256 + threadIdx.x;  // over 18432
    if (idx >= 36 * 8 * 64) return;
    int reg = idx & 1;
    int lane = (idx >> 1) & 31;
    int n8 = (idx >> 6) & 7;
    int k16 = idx >> 9;
    int n = n8 * 8 + (lane >> 2);
    int k0 = (lane & 3) * 2 + reg * 8;
    int kg = k16 * 16 + k0;
    int tap = kg >> 6;
    int c = kg & 63;
    float v0 = w[(n * CC + c) * 9 + tap];
    float v1 = w[(n * CC + c + 1) * 9 + tap];
    g_wfrag[idx] = (uint32_t)f16(v0) | ((uint32_t)f16(v1) << 16);
}

// ---------------------------------------------------------------------------
// Kernel 2b: offset weight (18,64,3,3) -> fragments, per-tap K chunks of 64.
// ---------------------------------------------------------------------------
__global__ void k_wofrag(const float* __restrict__ ow) {
    int idx = blockIdx.x * 256 + threadIdx.x;  // over 6912
    if (idx >= 9 * 4 * 3 * 64) return;
    int reg = idx & 1;
    int t = idx >> 1;
    int lane = t & 31;
    t >>= 5;
    int n8 = t % 3;
    t /= 3;
    int k16 = t & 3;
    int tap = t >> 2;
    int n = n8 * 8 + (lane >> 2);
    int c = k16 * 16 + (lane & 3) * 2 + reg * 8;
    float v0 = 0.f, v1 = 0.f;
    if (n < 18) {
        v0 = ow[(n * CC + c) * 9 + tap];
        v1 = ow[(n * CC + c + 1) * 9 + tap];
    }
    g_wofrag[idx] = (uint32_t)f16(v0) | ((uint32_t)f16(v1) << 16);
}

// ---------------------------------------------------------------------------
// Kernel 3: fused main kernel. grid (W/16, H, B), block 128, 7 blocks/SM.
// Stage A: x rows i-1..i+1 x 18 cols -> fp16 (overlay on samp).
// Stage B: warps 0-2: offset conv via mma (1 MMA per tap x k16).
// Stage C: bilinear gather -> fp16 samp[16][KPAD].
// Stage D: main contraction: per warp 2 n8 tiles, 36 k16 x 2 MMAs.
// ---------------------------------------------------------------------------
__global__ __launch_bounds__(128, 7) void k_main(const float* __restrict__ bias,
                                                 const float* __restrict__ off_b,
                                                 float* __restrict__ out) {
    __shared__ __align__(16) unsigned short samp[16 * KPAD];  // 18688 B
    __shared__ float offs[16][18];

    int tid = threadIdx.x;
    int b = blockIdx.z, i = blockIdx.y, j0 = blockIdx.x * 16;
    int wid = tid >> 5, lane = tid & 31;
    const float* xb = g_x + (size_t)b * HH * WW * CC;

    // ---- Stage A: x rows i-1..i+1, cols j0-1..j0+16, fp16, 144B rows --------
    unsigned short* xrow = samp;  // 3*18*72 = 3888 ushort (overlay)
    for (int idx = tid; idx < 3 * 18 * 16; idx += 128) {
        int row = idx / 288;
        int rem = idx - row * 288;
        int col = rem >> 4, q = rem & 15;
        int y = i + row - 1, x = j0 + col - 1;
        float4 v = make_float4(0.f, 0.f, 0.f, 0.f);
        if ((unsigned)y < HH && (unsigned)x < WW)
            v = *(const float4*)(xb + ((size_t)y * WW + x) * CC + q * 4);
        int o = (row * 18 + col) * XRP + q * 4;
        *(uint2*)&xrow[o] =
            make_uint2((uint32_t)f16(v.x) | ((uint32_t)f16(v.y) << 16),
                       (uint32_t)f16(v.z) | ((uint32_t)f16(v.w) << 16));
    }
    __syncthreads();

    // ---- Stage B: offset conv via mma (warps 0..2), 2 alternating chains ----
    if (wid < 3) {
        float da[4] = {0.f, 0.f, 0.f, 0.f};
        float db[4] = {0.f, 0.f, 0.f, 0.f};
        uint32_t la = (uint32_t)((lane & 15) * XRP + (lane >> 4) * 8) * 2;
        uint32_t aB0 = smem_u32(xrow) + la;
        const uint2* wf = (const uint2*)g_wofrag;
#pragma unroll 3
        for (int tap = 0; tap < 9; tap++) {
            int dy = tap / 3, dx = tap - dy * 3;
            uint32_t toff = (uint32_t)((dy * 18 + dx) * XRP) * 2;
#pragma unroll
            for (int k16 = 0; k16 < 4; k16++) {
                uint32_t aA[4];
                ldmat4(aA, aB0 + toff + k16 * 32);
                uint2 bW = wf[(((tap * 4 + k16) * 3 + wid)) * 32 + lane];
                if (k16 & 1) mma16816(db, aA, bW);
                else mma16816(da, aA, bW);
            }
        }
        int oc0 = wid * 8 + (lane & 3) * 2;
        int r0 = lane >> 2;
        if (oc0 + 1 < 18) {
            float b0 = __ldg(&off_b[oc0]), b1 = __ldg(&off_b[oc0 + 1]);
            offs[r0][oc0] = da[0] + db[0] + b0;
            offs[r0][oc0 + 1] = da[1] + db[1] + b1;
            offs[r0 + 8][oc0] = da[2] + db[2] + b0;
            offs[r0 + 8][oc0 + 1] = da[3] + db[3] + b1;
        }
    }
    __syncthreads();

    // ---- Stage C: gather, compile-time taps -> fp16 samp --------------------
    {
        int g = tid >> 4, ln = tid & 15;
#pragma unroll
        for (int half = 0; half < 2; half++) {
            int p = g + 8 * half;
            const float* po = offs[p];
            float py = (float)i;
            float px = (float)(j0 + p);
            unsigned short* dst = &samp[p * KPAD + ln * 4];
#pragma unroll
            for (int k = 0; k < 9; k++) {
                float oy = po[2 * k], ox = po[2 * k + 1];
                float sy = py + (float)(k / 3) + oy;
                float sx = px + (float)(k % 3) + ox;
                float fy = floorf(sy), fx = floorf(sx);
                float wy1 = sy - fy, wx1 = sx - fx;
                float wy0 = 1.f - wy1, wx0 = 1.f - wx1;
                int iy = (int)fy, ix = (int)fx;
                float tw0 = wy0 * wx0, tw1 = wy0 * wx1;
                float tw2 = wy1 * wx0, tw3 = wy1 * wx1;
                const float* r0 = xb + ((size_t)iy * WW + ix) * CC + ln * 4;
                float acc0 = 0.f, acc1 = 0.f, acc2 = 0.f, acc3 = 0.f;
                bool vy0 = (unsigned)iy < HH, vy1 = (unsigned)(iy + 1) < HH;
                bool vx0 = (unsigned)ix < WW, vx1 = (unsigned)(ix + 1) < WW;
                if (vy0 & vx0) {
                    float4 v = *(const float4*)r0;
                    acc0 += tw0 * v.x; acc1 += tw0 * v.y;
                    acc2 += tw0 * v.z; acc3 += tw0 * v.w;
                }
                if (vy0 & vx1) {
                    float4 v = *(const float4*)(r0 + CC);
                    acc0 += tw1 * v.x; acc1 += tw1 * v.y;
                    acc2 += tw1 * v.z; acc3 += tw1 * v.w;
                }
                if (vy1 & vx0) {
                    float4 v = *(const float4*)(r0 + WW * CC);
                    acc0 += tw2 * v.x; acc1 += tw2 * v.y;
                    acc2 += tw2 * v.z; acc3 += tw2 * v.w;
                }
                if (vy1 & vx1) {
                    float4 v = *(const float4*)(r0 + WW * CC + CC);
                    acc0 += tw3 * v.x; acc1 += tw3 * v.y;
                    acc2 += tw3 * v.z; acc3 += tw3 * v.w;
                }
                *(uint2*)&dst[k * 64] =
                    make_uint2((uint32_t)f16(acc0) | ((uint32_t)f16(acc1) << 16),
                               (uint32_t)f16(acc2) | ((uint32_t)f16(acc3) << 16));
            }
        }
    }
    __syncthreads();

    // ---- Stage D: main contraction, 2 MMAs per k16 --------------------------
    int arow = lane & 15;
    int akoff = (lane >> 4) * 8;
    uint32_t aBase = smem_u32(samp) + (uint32_t)(arow * KPAD + akoff) * 2;

    float d0a[4] = {0.f, 0.f, 0.f, 0.f};  // n8=2wid,   even k16
    float d0b[4] = {0.f, 0.f, 0.f, 0.f};  // n8=2wid,   odd k16
    float d1a[4] = {0.f, 0.f, 0.f, 0.f};  // n8=2wid+1, even k16
    float d1b[4] = {0.f, 0.f, 0.f, 0.f};  // n8=2wid+1, odd k16
    const uint2* wf = (const uint2*)g_wfrag;

#pragma unroll 6
    for (int k16 = 0; k16 < 36; k16++) {
        uint32_t aA[4];
        ldmat4(aA, aBase + k16 * 32);
        int base = k16 * 8 + wid * 2;
        uint2 b0 = wf[(base + 0) * 32 + lane];
        uint2 b1 = wf[(base + 1) * 32 + lane];
        if (k16 & 1) {
            mma16816(d0b, aA, b0);
            mma16816(d1b, aA, b1);
        } else {
            mma16816(d0a, aA, b0);
            mma16816(d1a, aA, b1);
        }
    }

    __syncthreads();  // samp fully consumed; reuse as f32 reduction buffer
    float* red = (float*)samp;  // 16 px x 64 o = 4096 floats (16 KB, fits)
    {
        int row = lane >> 2;
        int o0 = wid * 16 + (lane & 3) * 2;
        red[row * 64 + o0] = d0a[0] + d0b[0];
        red[row * 64 + o0 + 1] = d0a[1] + d0b[1];
        red[(row + 8) * 64 + o0] = d0a[2] + d0b[2];
        red[(row + 8) * 64 + o0 + 1] = d0a[3] + d0b[3];
        red[row * 64 + o0 + 8] = d1a[0] + d1b[0];
        red[row * 64 + o0 + 9] = d1a[1] + d1b[1];
        red[(row + 8) * 64 + o0 + 8] = d1a[2] + d1b[2];
        red[(row + 8) * 64 + o0 + 9] = d1a[3] + d1b[3];
    }
    __syncthreads();

    // coalesced NCHW store + bias
    for (int idx = tid; idx < 1024; idx += 128) {
        int oo = idx >> 4, p = idx & 15;
        float v = red[p * 64 + oo] + __ldg(&bias[oo]);
        out[((size_t)(b * OO + oo) * HH + i) * WW + j0 + p] = v;
    }
}

// ---------------------------------------------------------------------------
extern "C" void kernel_launch(void* const* d_in, const int* in_sizes, int n_in,
                              void* d_out, int out_size) {
    const float* x = (const float*)d_in[0];
    const float* weight = (const float*)d_in[1];
    const float* bias = (const float*)d_in[2];
    const float* off_w = (const float*)d_in[3];
    const float* off_b = (const float*)d_in[4];
    float* out = (float*)d_out;

    k_transpose<<<dim3(BB * HH, WW / 32, CC / 32), dim3(32, 8)>>>(x);
    k_wfrag<<<(36 * 8 * 64 + 255) / 256, 256>>>(weight);
    k_wofrag<<<(9 * 4 * 3 * 64 + 255) / 256, 256>>>(off_w);
    k_main<<<dim3(WW / 16, HH, BB), 128>>>(bias, off_b, out);
}

// round 16
// speedup vs baseline: 3.0432x; 1.1064x over previous
#include <cuda_runtime.h>
#include <cuda_fp16.h>
#include <cstdint>

// ---------------------------------------------------------------------------
// DeformableConv2d: B=8, C=64, H=W=128, O=64, K=3, stride=1, pad=1, dil=1
// Fully tensor-core, all-fp16 operands, fp32 accum. R15: g_x stored fp16
// (gather wavefronts halved); bilinear interp converts to f32 per corner.
// Calibrated error: ~sqrt(3/2) x 3.37e-4 ~= 4.1e-4 << 1e-3.
// ---------------------------------------------------------------------------

#define BB 8
#define CC 64
#define HH 128
#define WW 128
#define OO 64
#define KPAD 584  // 576 + 8 pad (ushort); row stride 1168B, 16B-aligned
#define XRP 72    // xrow pad: 64 ch + 8 -> 144B row stride, conflict-free ldmatrix

// Scratch (static device globals; no runtime allocation)
__device__ unsigned short g_x[(size_t)BB * HH * WW * CC];  // x in NHWC, fp16 bits
// main-weight fragments: [k16(36)][n8(8)][lane(32)][reg(2)]
__device__ uint32_t g_wfrag[36 * 8 * 32 * 2];
// offset-weight fragments: [tap(9)][k16(4)][n8(3)][lane(32)][reg(2)]
__device__ uint32_t g_wofrag[9 * 4 * 3 * 32 * 2];

// ---- tensor-core helpers ---------------------------------------------------
__device__ __forceinline__ void ldmat4(uint32_t* a, uint32_t addr) {
    asm volatile("ldmatrix.sync.aligned.m8n8.x4.shared.b16 {%0,%1,%2,%3}, [%4];"
                 : "=r"(a[0]), "=r"(a[1]), "=r"(a[2]), "=r"(a[3]) : "r"(addr));
}
__device__ __forceinline__ void mma16816(float* d, const uint32_t* a, uint2 b) {
    asm volatile(
        "mma.sync.aligned.m16n8k16.row.col.f32.f16.f16.f32 "
        "{%0,%1,%2,%3}, {%4,%5,%6,%7}, {%8,%9}, {%0,%1,%2,%3};"
        : "+f"(d[0]), "+f"(d[1]), "+f"(d[2]), "+f"(d[3])
        : "r"(a[0]), "r"(a[1]), "r"(a[2]), "r"(a[3]), "r"(b.x), "r"(b.y));
}
__device__ __forceinline__ uint32_t smem_u32(const void* p) {
    uint32_t a;
    asm("{ .reg .u64 t; cvta.to.shared.u64 t, %1; cvt.u32.u64 %0, t; }" : "=r"(a) : "l"(p));
    return a;
}
__device__ __forceinline__ unsigned short f16(float v) {
    return __half_as_ushort(__float2half_rn(v));
}

// ---------------------------------------------------------------------------
// Kernel 1: NCHW f32 -> NHWC fp16 transpose of x
// ---------------------------------------------------------------------------
__global__ void k_transpose(const float* __restrict__ x) {
    __shared__ float tile[32][33];
    int bh = blockIdx.x;
    int w0 = blockIdx.y * 32;
    int c0 = blockIdx.z * 32;
    int b = bh >> 7;
    const float* src = x + ((size_t)(b * CC) * HH + (bh & 127)) * WW;
#pragma unroll
    for (int i = 0; i < 32; i += 8) {
        int c = c0 + threadIdx.y + i;
        tile[threadIdx.y + i][threadIdx.x] = src[(size_t)c * HH * WW + w0 + threadIdx.x];
    }
    __syncthreads();
    unsigned short* dst = g_x + (size_t)bh * WW * CC;
#pragma unroll
    for (int i = 0; i < 32; i += 8) {
        int w = w0 + threadIdx.y + i;
        dst[(size_t)w * CC + c0 + threadIdx.x] = f16(tile[threadIdx.x][threadIdx.y + i]);
    }
}

// ---------------------------------------------------------------------------
// Kernel 2: main weight -> mma.sync B fragments (single fp16).
// thread 'lane' reg r holds B[k0][n],B[k0+1][n]; k0=(lane&3)*2+r*8, n=n8*8+(lane>>2).
// ---------------------------------------------------------------------------
__global__ void k_wfrag(const float* __restrict__ w) {
    int idx = blockIdx.x * 256 + threadIdx.x;  // over 18432
    if (idx >= 36 * 8 * 64) return;
    int reg = idx & 1;
    int lane = (idx >> 1) & 31;
    int n8 = (idx >> 6) & 7;
    int k16 = idx >> 9;
    int n = n8 * 8 + (lane >> 2);
    int k0 = (lane & 3) * 2 + reg * 8;
    int kg = k16 * 16 + k0;
    int tap = kg >> 6;
    int c = kg & 63;
    float v0 = w[(n * CC + c) * 9 + tap];
    float v1 = w[(n * CC + c + 1) * 9 + tap];
    g_wfrag[idx] = (uint32_t)f16(v0) | ((uint32_t)f16(v1) << 16);
}

// ---------------------------------------------------------------------------
// Kernel 2b: offset weight (18,64,3,3) -> fragments, per-tap K chunks of 64.
// ---------------------------------------------------------------------------
__global__ void k_wofrag(const float* __restrict__ ow) {
    int idx = blockIdx.x * 256 + threadIdx.x;  // over 6912
    if (idx >= 9 * 4 * 3 * 64) return;
    int reg = idx & 1;
    int t = idx >> 1;
    int lane = t & 31;
    t >>= 5;
    int n8 = t % 3;
    t /= 3;
    int k16 = t & 3;
    int tap = t >> 2;
    int n = n8 * 8 + (lane >> 2);
    int c = k16 * 16 + (lane & 3) * 2 + reg * 8;
    float v0 = 0.f, v1 = 0.f;
    if (n < 18) {
        v0 = ow[(n * CC + c) * 9 + tap];
        v1 = ow[(n * CC + c + 1) * 9 + tap];
    }
    g_wofrag[idx] = (uint32_t)f16(v0) | ((uint32_t)f16(v1) << 16);
}

// ---------------------------------------------------------------------------
// Kernel 3: fused main kernel. grid (W/16, H, B), block 128, 7 blocks/SM.
// Stage A: x rows i-1..i+1 x 18 cols -> fp16 copy (overlay on samp).
// Stage B: warps 0-2: offset conv via mma (1 MMA per tap x k16).
// Stage C: bilinear gather from fp16 g_x (f32 accum) -> fp16 samp[16][KPAD].
// Stage D: main contraction: per warp 2 n8 tiles, 36 k16 x 2 MMAs.
// ---------------------------------------------------------------------------
__global__ __launch_bounds__(128, 7) void k_main(const float* __restrict__ bias,
                                                 const float* __restrict__ off_b,
                                                 float* __restrict__ out) {
    __shared__ __align__(16) unsigned short samp[16 * KPAD];  // 18688 B
    __shared__ float offs[16][18];

    int tid = threadIdx.x;
    int b = blockIdx.z, i = blockIdx.y, j0 = blockIdx.x * 16;
    int wid = tid >> 5, lane = tid & 31;
    const unsigned short* xb = g_x + (size_t)b * HH * WW * CC;

    // ---- Stage A: x rows i-1..i+1, cols j0-1..j0+16, fp16 copy, 144B rows ---
    unsigned short* xrow = samp;  // 3*18*72 = 3888 ushort (overlay)
    for (int idx = tid; idx < 3 * 18 * 16; idx += 128) {
        int row = idx / 288;
        int rem = idx - row * 288;
        int col = rem >> 4, q = rem & 15;
        int y = i + row - 1, x = j0 + col - 1;
        uint2 v = make_uint2(0u, 0u);
        if ((unsigned)y < HH && (unsigned)x < WW)
            v = *(const uint2*)&xb[((size_t)y * WW + x) * CC + q * 4];
        *(uint2*)&xrow[(row * 18 + col) * XRP + q * 4] = v;
    }
    __syncthreads();

    // ---- Stage B: offset conv via mma (warps 0..2), 2 alternating chains ----
    if (wid < 3) {
        float da[4] = {0.f, 0.f, 0.f, 0.f};
        float db[4] = {0.f, 0.f, 0.f, 0.f};
        uint32_t la = (uint32_t)((lane & 15) * XRP + (lane >> 4) * 8) * 2;
        uint32_t aB0 = smem_u32(xrow) + la;
        const uint2* wf = (const uint2*)g_wofrag;
#pragma unroll 3
        for (int tap = 0; tap < 9; tap++) {
            int dy = tap / 3, dx = tap - dy * 3;
            uint32_t toff = (uint32_t)((dy * 18 + dx) * XRP) * 2;
#pragma unroll
            for (int k16 = 0; k16 < 4; k16++) {
                uint32_t aA[4];
                ldmat4(aA, aB0 + toff + k16 * 32);
                uint2 bW = wf[(((tap * 4 + k16) * 3 + wid)) * 32 + lane];
                if (k16 & 1) mma16816(db, aA, bW);
                else mma16816(da, aA, bW);
            }
        }
        int oc0 = wid * 8 + (lane & 3) * 2;
        int r0 = lane >> 2;
        if (oc0 + 1 < 18) {
            float b0 = __ldg(&off_b[oc0]), b1 = __ldg(&off_b[oc0 + 1]);
            offs[r0][oc0] = da[0] + db[0] + b0;
            offs[r0][oc0 + 1] = da[1] + db[1] + b1;
            offs[r0 + 8][oc0] = da[2] + db[2] + b0;
            offs[r0 + 8][oc0 + 1] = da[3] + db[3] + b1;
        }
    }
    __syncthreads();

    // ---- Stage C: gather from fp16 x, f32 accum -> fp16 samp ----------------
    {
        int g = tid >> 4, ln = tid & 15;
#pragma unroll
        for (int half = 0; half < 2; half++) {
            int p = g + 8 * half;
            const float* po = offs[p];
            float py = (float)i;
            float px = (float)(j0 + p);
            unsigned short* dst = &samp[p * KPAD + ln * 4];
#pragma unroll
            for (int k = 0; k < 9; k++) {
                float oy = po[2 * k], ox = po[2 * k + 1];
                float sy = py + (float)(k / 3) + oy;
                float sx = px + (float)(k % 3) + ox;
                float fy = floorf(sy), fx = floorf(sx);
                float wy1 = sy - fy, wx1 = sx - fx;
                float wy0 = 1.f - wy1, wx0 = 1.f - wx1;
                int iy = (int)fy, ix = (int)fx;
                float tw0 = wy0 * wx0, tw1 = wy0 * wx1;
                float tw2 = wy1 * wx0, tw3 = wy1 * wx1;
                const unsigned short* r0 = xb + ((size_t)iy * WW + ix) * CC + ln * 4;
                float acc0 = 0.f, acc1 = 0.f, acc2 = 0.f, acc3 = 0.f;
                bool vy0 = (unsigned)iy < HH, vy1 = (unsigned)(iy + 1) < HH;
                bool vx0 = (unsigned)ix < WW, vx1 = (unsigned)(ix + 1) < WW;
                if (vy0 & vx0) {
                    uint2 v = *(const uint2*)r0;
                    float2 a = __half22float2(*(__half2*)&v.x);
                    float2 c = __half22float2(*(__half2*)&v.y);
                    acc0 += tw0 * a.x; acc1 += tw0 * a.y;
                    acc2 += tw0 * c.x; acc3 += tw0 * c.y;
                }
                if (vy0 & vx1) {
                    uint2 v = *(const uint2*)(r0 + CC);
                    float2 a = __half22float2(*(__half2*)&v.x);
                    float2 c = __half22float2(*(__half2*)&v.y);
                    acc0 += tw1 * a.x; acc1 += tw1 * a.y;
                    acc2 += tw1 * c.x; acc3 += tw1 * c.y;
                }
                if (vy1 & vx0) {
                    uint2 v = *(const uint2*)(r0 + WW * CC);
                    float2 a = __half22float2(*(__half2*)&v.x);
                    float2 c = __half22float2(*(__half2*)&v.y);
                    acc0 += tw2 * a.x; acc1 += tw2 * a.y;
                    acc2 += tw2 * c.x; acc3 += tw2 * c.y;
                }
                if (vy1 & vx1) {
                    uint2 v = *(const uint2*)(r0 + WW * CC + CC);
                    float2 a = __half22float2(*(__half2*)&v.x);
                    float2 c = __half22float2(*(__half2*)&v.y);
                    acc0 += tw3 * a.x; acc1 += tw3 * a.y;
                    acc2 += tw3 * c.x; acc3 += tw3 * c.y;
                }
                *(uint2*)&dst[k * 64] =
                    make_uint2((uint32_t)f16(acc0) | ((uint32_t)f16(acc1) << 16),
                               (uint32_t)f16(acc2) | ((uint32_t)f16(acc3) << 16));
            }
        }
    }
    __syncthreads();

    // ---- Stage D: main contraction, 2 MMAs per k16 --------------------------
    int arow = lane & 15;
    int akoff = (lane >> 4) * 8;
    uint32_t aBase = smem_u32(samp) + (uint32_t)(arow * KPAD + akoff) * 2;

    float d0a[4] = {0.f, 0.f, 0.f, 0.f};  // n8=2wid,   even k16
    float d0b[4] = {0.f, 0.f, 0.f, 0.f};  // n8=2wid,   odd k16
    float d1a[4] = {0.f, 0.f, 0.f, 0.f};  // n8=2wid+1, even k16
    float d1b[4] = {0.f, 0.f, 0.f, 0.f};  // n8=2wid+1, odd k16
    const uint2* wf = (const uint2*)g_wfrag;

#pragma unroll 6
    for (int k16 = 0; k16 < 36; k16++) {
        uint32_t aA[4];
        ldmat4(aA, aBase + k16 * 32);
        int base = k16 * 8 + wid * 2;
        uint2 b0 = wf[(base + 0) * 32 + lane];
        uint2 b1 = wf[(base + 1) * 32 + lane];
        if (k16 & 1) {
            mma16816(d0b, aA, b0);
            mma16816(d1b, aA, b1);
        } else {
            mma16816(d0a, aA, b0);
            mma16816(d1a, aA, b1);
        }
    }

    __syncthreads();  // samp fully consumed; reuse as f32 reduction buffer
    float* red = (float*)samp;  // 16 px x 64 o = 4096 floats (16 KB, fits)
    {
        int row = lane >> 2;
        int o0 = wid * 16 + (lane & 3) * 2;
        red[row * 64 + o0] = d0a[0] + d0b[0];
        red[row * 64 + o0 + 1] = d0a[1] + d0b[1];
        red[(row + 8) * 64 + o0] = d0a[2] + d0b[2];
        red[(row + 8) * 64 + o0 + 1] = d0a[3] + d0b[3];
        red[row * 64 + o0 + 8] = d1a[0] + d1b[0];
        red[row * 64 + o0 + 9] = d1a[1] + d1b[1];
        red[(row + 8) * 64 + o0 + 8] = d1a[2] + d1b[2];
        red[(row + 8) * 64 + o0 + 9] = d1a[3] + d1b[3];
    }
    __syncthreads();

    // coalesced NCHW store + bias
    for (int idx = tid; idx < 1024; idx += 128) {
        int oo = idx >> 4, p = idx & 15;
        float v = red[p * 64 + oo] + __ldg(&bias[oo]);
        out[((size_t)(b * OO + oo) * HH + i) * WW + j0 + p] = v;
    }
}

// ---------------------------------------------------------------------------
extern "C" void kernel_launch(void* const* d_in, const int* in_sizes, int n_in,
                              void* d_out, int out_size) {
    const float* x = (const float*)d_in[0];
    const float* weight = (const float*)d_in[1];
    const float* bias = (const float*)d_in[2];
    const float* off_w = (const float*)d_in[3];
    const float* off_b = (const float*)d_in[4];
    float* out = (float*)d_out;

    k_transpose<<<dim3(BB * HH, WW / 32, CC / 32), dim3(32, 8)>>>(x);
    k_wfrag<<<(36 * 8 * 64 + 255) / 256, 256>>>(weight);
    k_wofrag<<<(9 * 4 * 3 * 64 + 255) / 256, 256>>>(off_w);
    k_main<<<dim3(WW / 16, HH, BB), 128>>>(bias, off_b, out);
}

// round 17
// speedup vs baseline: 3.2083x; 1.0542x over previous
#include <cuda_runtime.h>
#include <cuda_fp16.h>
#include <cstdint>

// ---------------------------------------------------------------------------
// DeformableConv2d: B=8, C=64, H=W=128, O=64, K=3, stride=1, pad=1, dil=1
// Fully tensor-core, all-fp16 operands, fp32 MMA accum. R16: bilinear interp
// in half2 (HFMA2) and fused uint4 B-fragment loads.
// Calibrated error: ~sqrt(5) x 2.38e-4 ~= 5.3e-4 < 1e-3.
// ---------------------------------------------------------------------------

#define BB 8
#define CC 64
#define HH 128
#define WW 128
#define OO 64
#define KPAD 584  // 576 + 8 pad (ushort); row stride 1168B, 16B-aligned
#define XRP 72    // xrow pad: 64 ch + 8 -> 144B row stride, conflict-free ldmatrix

// Scratch (static device globals; no runtime allocation)
__device__ unsigned short g_x[(size_t)BB * HH * WW * CC];  // x in NHWC, fp16 bits
// main-weight fragments, fused: [k16(36)][nw(4)][lane(32)][word(4)]
// word = {b0.reg0, b0.reg1, b1.reg0, b1.reg1} for the warp's n8 pair {2nw,2nw+1}
__device__ uint32_t g_wfrag[36 * 4 * 32 * 4];
// offset-weight fragments: [tap(9)][k16(4)][n8(3)][lane(32)][reg(2)]
__device__ uint32_t g_wofrag[9 * 4 * 3 * 32 * 2];

// ---- tensor-core helpers ---------------------------------------------------
__device__ __forceinline__ void ldmat4(uint32_t* a, uint32_t addr) {
    asm volatile("ldmatrix.sync.aligned.m8n8.x4.shared.b16 {%0,%1,%2,%3}, [%4];"
                 : "=r"(a[0]), "=r"(a[1]), "=r"(a[2]), "=r"(a[3]) : "r"(addr));
}
__device__ __forceinline__ void mma16816(float* d, const uint32_t* a, uint32_t bx,
                                         uint32_t by) {
    asm volatile(
        "mma.sync.aligned.m16n8k16.row.col.f32.f16.f16.f32 "
        "{%0,%1,%2,%3}, {%4,%5,%6,%7}, {%8,%9}, {%0,%1,%2,%3};"
        : "+f"(d[0]), "+f"(d[1]), "+f"(d[2]), "+f"(d[3])
        : "r"(a[0]), "r"(a[1]), "r"(a[2]), "r"(a[3]), "r"(bx), "r"(by));
}
__device__ __forceinline__ uint32_t smem_u32(const void* p) {
    uint32_t a;
    asm("{ .reg .u64 t; cvta.to.shared.u64 t, %1; cvt.u32.u64 %0, t; }" : "=r"(a) : "l"(p));
    return a;
}
__device__ __forceinline__ unsigned short f16(float v) {
    return __half_as_ushort(__float2half_rn(v));
}

// ---------------------------------------------------------------------------
// Kernel 1: NCHW f32 -> NHWC fp16 transpose of x
// ---------------------------------------------------------------------------
__global__ void k_transpose(const float* __restrict__ x) {
    __shared__ float tile[32][33];
    int bh = blockIdx.x;
    int w0 = blockIdx.y * 32;
    int c0 = blockIdx.z * 32;
    int b = bh >> 7;
    const float* src = x + ((size_t)(b * CC) * HH + (bh & 127)) * WW;
#pragma unroll
    for (int i = 0; i < 32; i += 8) {
        int c = c0 + threadIdx.y + i;
        tile[threadIdx.y + i][threadIdx.x] = src[(size_t)c * HH * WW + w0 + threadIdx.x];
    }
    __syncthreads();
    unsigned short* dst = g_x + (size_t)bh * WW * CC;
#pragma unroll
    for (int i = 0; i < 32; i += 8) {
        int w = w0 + threadIdx.y + i;
        dst[(size_t)w * CC + c0 + threadIdx.x] = f16(tile[threadIdx.x][threadIdx.y + i]);
    }
}

// ---------------------------------------------------------------------------
// Kernel 2: main weight -> fused mma.sync B fragments (single fp16).
// word w of lane: n8 = nw*2 + (w>>1), reg r = w&1 holds B[k0][n],B[k0+1][n];
// k0=(lane&3)*2+r*8, n=n8*8+(lane>>2). K dim = tap*64 + c.
// ---------------------------------------------------------------------------
__global__ void k_wfrag(const float* __restrict__ w) {
    int idx = blockIdx.x * 256 + threadIdx.x;  // over 18432
    if (idx >= 36 * 4 * 32 * 4) return;
    int word = idx & 3;
    int lane = (idx >> 2) & 31;
    int nw = (idx >> 7) & 3;
    int k16 = idx >> 9;
    int n8 = nw * 2 + (word >> 1);
    int reg = word & 1;
    int n = n8 * 8 + (lane >> 2);
    int k0 = (lane & 3) * 2 + reg * 8;
    int kg = k16 * 16 + k0;
    int tap = kg >> 6;
    int c = kg & 63;
    float v0 = w[(n * CC + c) * 9 + tap];
    float v1 = w[(n * CC + c + 1) * 9 + tap];
    g_wfrag[idx] = (uint32_t)f16(v0) | ((uint32_t)f16(v1) << 16);
}

// ---------------------------------------------------------------------------
// Kernel 2b: offset weight (18,64,3,3) -> fragments, per-tap K chunks of 64.
// ---------------------------------------------------------------------------
__global__ void k_wofrag(const float* __restrict__ ow) {
    int idx = blockIdx.x * 256 + threadIdx.x;  // over 6912
    if (idx >= 9 * 4 * 3 * 64) return;
    int reg = idx & 1;
    int t = idx >> 1;
    int lane = t & 31;
    t >>= 5;
    int n8 = t % 3;
    t /= 3;
    int k16 = t & 3;
    int tap = t >> 2;
    int n = n8 * 8 + (lane >> 2);
    int c = k16 * 16 + (lane & 3) * 2 + reg * 8;
    float v0 = 0.f, v1 = 0.f;
    if (n < 18) {
        v0 = ow[(n * CC + c) * 9 + tap];
        v1 = ow[(n * CC + c + 1) * 9 + tap];
    }
    g_wofrag[idx] = (uint32_t)f16(v0) | ((uint32_t)f16(v1) << 16);
}

// ---------------------------------------------------------------------------
// Kernel 3: fused main kernel. grid (W/16, H, B), block 128, 7 blocks/SM.
// Stage A: x rows i-1..i+1 x 18 cols -> fp16 copy (overlay on samp).
// Stage B: warps 0-2: offset conv via mma (1 MMA per tap x k16).
// Stage C: bilinear gather, half2 HFMA2 interp -> fp16 samp[16][KPAD].
// Stage D: main contraction: per warp 2 n8 tiles, 36 k16 x 2 MMAs,
//          fused uint4 B-fragment load.
// ---------------------------------------------------------------------------
__global__ __launch_bounds__(128, 7) void k_main(const float* __restrict__ bias,
                                                 const float* __restrict__ off_b,
                                                 float* __restrict__ out) {
    __shared__ __align__(16) unsigned short samp[16 * KPAD];  // 18688 B
    __shared__ float offs[16][18];

    int tid = threadIdx.x;
    int b = blockIdx.z, i = blockIdx.y, j0 = blockIdx.x * 16;
    int wid = tid >> 5, lane = tid & 31;
    const unsigned short* xb = g_x + (size_t)b * HH * WW * CC;

    // ---- Stage A: x rows i-1..i+1, cols j0-1..j0+16, fp16 copy, 144B rows ---
    unsigned short* xrow = samp;  // 3*18*72 = 3888 ushort (overlay)
    for (int idx = tid; idx < 3 * 18 * 16; idx += 128) {
        int row = idx / 288;
        int rem = idx - row * 288;
        int col = rem >> 4, q = rem & 15;
        int y = i + row - 1, x = j0 + col - 1;
        uint2 v = make_uint2(0u, 0u);
        if ((unsigned)y < HH && (unsigned)x < WW)
            v = *(const uint2*)&xb[((size_t)y * WW + x) * CC + q * 4];
        *(uint2*)&xrow[(row * 18 + col) * XRP + q * 4] = v;
    }
    __syncthreads();

    // ---- Stage B: offset conv via mma (warps 0..2), 2 alternating chains ----
    if (wid < 3) {
        float da[4] = {0.f, 0.f, 0.f, 0.f};
        float db[4] = {0.f, 0.f, 0.f, 0.f};
        uint32_t la = (uint32_t)((lane & 15) * XRP + (lane >> 4) * 8) * 2;
        uint32_t aB0 = smem_u32(xrow) + la;
        const uint2* wf = (const uint2*)g_wofrag;
#pragma unroll 3
        for (int tap = 0; tap < 9; tap++) {
            int dy = tap / 3, dx = tap - dy * 3;
            uint32_t toff = (uint32_t)((dy * 18 + dx) * XRP) * 2;
#pragma unroll
            for (int k16 = 0; k16 < 4; k16++) {
                uint32_t aA[4];
                ldmat4(aA, aB0 + toff + k16 * 32);
                uint2 bW = wf[(((tap * 4 + k16) * 3 + wid)) * 32 + lane];
                if (k16 & 1) mma16816(db, aA, bW.x, bW.y);
                else mma16816(da, aA, bW.x, bW.y);
            }
        }
        int oc0 = wid * 8 + (lane & 3) * 2;
        int r0 = lane >> 2;
        if (oc0 + 1 < 18) {
            float b0 = __ldg(&off_b[oc0]), b1 = __ldg(&off_b[oc0 + 1]);
            offs[r0][oc0] = da[0] + db[0] + b0;
            offs[r0][oc0 + 1] = da[1] + db[1] + b1;
            offs[r0 + 8][oc0] = da[2] + db[2] + b0;
            offs[r0 + 8][oc0 + 1] = da[3] + db[3] + b1;
        }
    }
    __syncthreads();

    // ---- Stage C: gather, half2 HFMA2 interp -> fp16 samp -------------------
    {
        int g = tid >> 4, ln = tid & 15;
#pragma unroll
        for (int half = 0; half < 2; half++) {
            int p = g + 8 * half;
            const float* po = offs[p];
            float py = (float)i;
            float px = (float)(j0 + p);
            unsigned short* dst = &samp[p * KPAD + ln * 4];
#pragma unroll
            for (int k = 0; k < 9; k++) {
                float oy = po[2 * k], ox = po[2 * k + 1];
                float sy = py + (float)(k / 3) + oy;
                float sx = px + (float)(k % 3) + ox;
                float fy = floorf(sy), fx = floorf(sx);
                float wy1 = sy - fy, wx1 = sx - fx;
                float wy0 = 1.f - wy1, wx0 = 1.f - wx1;
                int iy = (int)fy, ix = (int)fx;
                __half2 w0 = __float2half2_rn(wy0 * wx0);
                __half2 w1 = __float2half2_rn(wy0 * wx1);
                __half2 w2 = __float2half2_rn(wy1 * wx0);
                __half2 w3 = __float2half2_rn(wy1 * wx1);
                const unsigned short* r0 = xb + ((size_t)iy * WW + ix) * CC + ln * 4;
                __half2 acc01 = __float2half2_rn(0.f);
                __half2 acc23 = __float2half2_rn(0.f);
                bool vy0 = (unsigned)iy < HH, vy1 = (unsigned)(iy + 1) < HH;
                bool vx0 = (unsigned)ix < WW, vx1 = (unsigned)(ix + 1) < WW;
                if (vy0 & vx0) {
                    uint2 v = *(const uint2*)r0;
                    acc01 = __hfma2(w0, *(__half2*)&v.x, acc01);
                    acc23 = __hfma2(w0, *(__half2*)&v.y, acc23);
                }
                if (vy0 & vx1) {
                    uint2 v = *(const uint2*)(r0 + CC);
                    acc01 = __hfma2(w1, *(__half2*)&v.x, acc01);
                    acc23 = __hfma2(w1, *(__half2*)&v.y, acc23);
                }
                if (vy1 & vx0) {
                    uint2 v = *(const uint2*)(r0 + WW * CC);
                    acc01 = __hfma2(w2, *(__half2*)&v.x, acc01);
                    acc23 = __hfma2(w2, *(__half2*)&v.y, acc23);
                }
                if (vy1 & vx1) {
                    uint2 v = *(const uint2*)(r0 + WW * CC + CC);
                    acc01 = __hfma2(w3, *(__half2*)&v.x, acc01);
                    acc23 = __hfma2(w3, *(__half2*)&v.y, acc23);
                }
                *(uint2*)&dst[k * 64] = make_uint2(*(uint32_t*)&acc01,
                                                   *(uint32_t*)&acc23);
            }
        }
    }
    __syncthreads();

    // ---- Stage D: main contraction, fused uint4 B loads, 2 MMAs per k16 -----
    int arow = lane & 15;
    int akoff = (lane >> 4) * 8;
    uint32_t aBase = smem_u32(samp) + (uint32_t)(arow * KPAD + akoff) * 2;

    float d0a[4] = {0.f, 0.f, 0.f, 0.f};  // n8=2wid,   even k16
    float d0b[4] = {0.f, 0.f, 0.f, 0.f};  // n8=2wid,   odd k16
    float d1a[4] = {0.f, 0.f, 0.f, 0.f};  // n8=2wid+1, even k16
    float d1b[4] = {0.f, 0.f, 0.f, 0.f};  // n8=2wid+1, odd k16
    const uint4* wf = (const uint4*)g_wfrag;  // [k16][nw][lane]

#pragma unroll 6
    for (int k16 = 0; k16 < 36; k16++) {
        uint32_t aA[4];
        ldmat4(aA, aBase + k16 * 32);
        uint4 bb = wf[(k16 * 4 + wid) * 32 + lane];
        if (k16 & 1) {
            mma16816(d0b, aA, bb.x, bb.y);
            mma16816(d1b, aA, bb.z, bb.w);
        } else {
            mma16816(d0a, aA, bb.x, bb.y);
            mma16816(d1a, aA, bb.z, bb.w);
        }
    }

    __syncthreads();  // samp fully consumed; reuse as f32 reduction buffer
    float* red = (float*)samp;  // 16 px x 64 o = 4096 floats (16 KB, fits)
    {
        int row = lane >> 2;
        int o0 = wid * 16 + (lane & 3) * 2;
        red[row * 64 + o0] = d0a[0] + d0b[0];
        red[row * 64 + o0 + 1] = d0a[1] + d0b[1];
        red[(row + 8) * 64 + o0] = d0a[2] + d0b[2];
        red[(row + 8) * 64 + o0 + 1] = d0a[3] + d0b[3];
        red[row * 64 + o0 + 8] = d1a[0] + d1b[0];
        red[row * 64 + o0 + 9] = d1a[1] + d1b[1];
        red[(row + 8) * 64 + o0 + 8] = d1a[2] + d1b[2];
        red[(row + 8) * 64 + o0 + 9] = d1a[3] + d1b[3];
    }
    __syncthreads();

    // coalesced NCHW store + bias
    for (int idx = tid; idx < 1024; idx += 128) {
        int oo = idx >> 4, p = idx & 15;
        float v = red[p * 64 + oo] + __ldg(&bias[oo]);
        out[((size_t)(b * OO + oo) * HH + i) * WW + j0 + p] = v;
    }
}

// ---------------------------------------------------------------------------
extern "C" void kernel_launch(void* const* d_in, const int* in_sizes, int n_in,
                              void* d_out, int out_size) {
    const float* x = (const float*)d_in[0];
    const float* weight = (const float*)d_in[1];
    const float* bias = (const float*)d_in[2];
    const float* off_w = (const float*)d_in[3];
    const float* off_b = (const float*)d_in[4];
    float* out = (float*)d_out;

    k_transpose<<<dim3(BB * HH, WW / 32, CC / 32), dim3(32, 8)>>>(x);
    k_wfrag<<<(36 * 4 * 32 * 4 + 255) / 256, 256>>>(weight);
    k_wofrag<<<(9 * 4 * 3 * 64 + 255) / 256, 256>>>(off_w);
    k_main<<<dim3(WW / 16, HH, BB), 128>>>(bias, off_b, out);
}